// round 3
// baseline (speedup 1.0000x reference)
#include <cuda_runtime.h>
#include <cuda_bf16.h>
#include <math.h>
#include <stdint.h>

#define D_MODEL 1024
#define NH      16
#define DHEAD   64
#define BATCH   4
#define SEQ     1024
#define MROWS   (BATCH * SEQ)   // 4096

// ---------------------------------------------------------------------------
// Scratch (static device globals — no allocation allowed). All bf16 split pairs.
// ---------------------------------------------------------------------------
#define NACT ((size_t)MROWS * D_MODEL)   // 4M
#define NW   ((size_t)D_MODEL * D_MODEL) // 1M
__device__ __nv_bfloat16 g_xq_h[NACT], g_xq_l[NACT];   // split input queries
__device__ __nv_bfloat16 g_xk_h[NACT], g_xk_l[NACT];   // split input keys
__device__ __nv_bfloat16 g_xv_h[NACT], g_xv_l[NACT];   // split input values
__device__ __nv_bfloat16 g_wq_h[NW], g_wq_l[NW];
__device__ __nv_bfloat16 g_wk_h[NW], g_wk_l[NW];
__device__ __nv_bfloat16 g_wv_h[NW], g_wv_l[NW];
__device__ __nv_bfloat16 g_wo_h[NW], g_wo_l[NW];
__device__ __nv_bfloat16 g_q_h[NACT], g_q_l[NACT];     // projected Q split
__device__ __nv_bfloat16 g_k_h[NACT], g_k_l[NACT];
__device__ __nv_bfloat16 g_v_h[NACT], g_v_l[NACT];
__device__ __nv_bfloat16 g_o_h[NACT], g_o_l[NACT];     // attention out split

// ---------------------------------------------------------------------------
// Helpers
// ---------------------------------------------------------------------------
__device__ __forceinline__ uint32_t smem_u32(const void* p) {
    return (uint32_t)__cvta_generic_to_shared(p);
}
__device__ __forceinline__ void cp_async16(uint32_t dst, const void* src) {
    asm volatile("cp.async.cg.shared.global [%0], [%1], 16;" :: "r"(dst), "l"(src));
}
__device__ __forceinline__ void cp_commit() {
    asm volatile("cp.async.commit_group;");
}
template <int N>
__device__ __forceinline__ void cp_wait() {
    asm volatile("cp.async.wait_group %0;" :: "n"(N));
}
__device__ __forceinline__ void ldsm_x4(uint32_t addr, uint32_t& r0, uint32_t& r1,
                                        uint32_t& r2, uint32_t& r3) {
    asm volatile("ldmatrix.sync.aligned.m8n8.x4.shared.b16 {%0,%1,%2,%3}, [%4];"
                 : "=r"(r0), "=r"(r1), "=r"(r2), "=r"(r3) : "r"(addr));
}
__device__ __forceinline__ void ldsm_x4_t(uint32_t addr, uint32_t& r0, uint32_t& r1,
                                          uint32_t& r2, uint32_t& r3) {
    asm volatile("ldmatrix.sync.aligned.m8n8.x4.trans.shared.b16 {%0,%1,%2,%3}, [%4];"
                 : "=r"(r0), "=r"(r1), "=r"(r2), "=r"(r3) : "r"(addr));
}
__device__ __forceinline__ void mma16816(float c[4], const uint32_t a[4], const uint32_t b[2]) {
    asm volatile(
        "mma.sync.aligned.m16n8k16.row.col.f32.bf16.bf16.f32 "
        "{%0,%1,%2,%3}, {%4,%5,%6,%7}, {%8,%9}, {%0,%1,%2,%3};"
        : "+f"(c[0]), "+f"(c[1]), "+f"(c[2]), "+f"(c[3])
        : "r"(a[0]), "r"(a[1]), "r"(a[2]), "r"(a[3]), "r"(b[0]), "r"(b[1]));
}
__device__ __forceinline__ void split_pack(float x, float y, uint32_t& hi, uint32_t& lo) {
    __nv_bfloat16 xh = __float2bfloat16_rn(x);
    __nv_bfloat16 yh = __float2bfloat16_rn(y);
    __nv_bfloat162 h2; h2.x = xh; h2.y = yh;
    hi = *reinterpret_cast<uint32_t*>(&h2);
    float xl = x - __bfloat162float(xh);
    float yl = y - __bfloat162float(yh);
    __nv_bfloat162 l2 = __floats2bfloat162_rn(xl, yl);
    lo = *reinterpret_cast<uint32_t*>(&l2);
}

// ---------------------------------------------------------------------------
// Elementwise fp32 -> (bf16 hi, bf16 lo) split.
// ---------------------------------------------------------------------------
__global__ __launch_bounds__(256)
void split_kernel(const float* __restrict__ in, __nv_bfloat16* __restrict__ hi,
                  __nv_bfloat16* __restrict__ lo, int n4)
{
    int idx = blockIdx.x * blockDim.x + threadIdx.x;
    if (idx >= n4) return;
    float4 v = ((const float4*)in)[idx];
    uint32_t h0, l0, h1, l1;
    split_pack(v.x, v.y, h0, l0);
    split_pack(v.z, v.w, h1, l1);
    *(uint2*)&hi[(size_t)idx * 4] = make_uint2(h0, h1);
    *(uint2*)&lo[(size_t)idx * 4] = make_uint2(l0, l1);
}

// ---------------------------------------------------------------------------
// GEMM on pre-split bf16: C = A @ W + bias. 128x128x32 tiles, 2-stage cp.async.
// SPLIT_OUT: write (Ch, Cl) bf16 split; else write fp32 C.
// ---------------------------------------------------------------------------
#define GBM 128
#define GBN 128
#define GBK 32
#define ASTR 40
#define BSTR 136
#define G_A_ELT (GBM * ASTR)          // 5120
#define G_B_ELT (GBK * BSTR)          // 4352
#define G_STAGE (2 * G_A_ELT + 2 * G_B_ELT)   // 18944 elts
#define G_SMEM_BYTES (2 * G_STAGE * 2)        // 75776 B

template <bool SPLIT_OUT>
__global__ __launch_bounds__(256)
void gemm_tc(const __nv_bfloat16* __restrict__ Ahg, const __nv_bfloat16* __restrict__ Alg,
             const __nv_bfloat16* __restrict__ Bhg, const __nv_bfloat16* __restrict__ Blg,
             const float* __restrict__ bias,
             float* __restrict__ C,
             __nv_bfloat16* __restrict__ Chg, __nv_bfloat16* __restrict__ Clg,
             int M, int N, int K)
{
    extern __shared__ __align__(16) __nv_bfloat16 dsm[];

    const int tid  = threadIdx.x;
    const int lane = tid & 31;
    const int warp = tid >> 5;
    const int g    = lane >> 2;
    const int tig  = lane & 3;
    const int wm   = (warp >> 2) * 64;
    const int wn   = (warp & 3) * 32;
    const int bm   = blockIdx.y * GBM;
    const int bn   = blockIdx.x * GBN;
    const int lm_r = (lane & 7) + ((lane >> 3) & 1) * 8;
    const int lm_c = (lane >> 4) * 8;

    float acc[4][4][4];
    #pragma unroll
    for (int i = 0; i < 4; i++)
        #pragma unroll
        for (int j = 0; j < 4; j++)
            #pragma unroll
            for (int t = 0; t < 4; t++) acc[i][j][t] = 0.0f;

    auto prefetch = [&](int k0, int s) {
        __nv_bfloat16* base = dsm + s * G_STAGE;
        __nv_bfloat16* sAh = base;
        __nv_bfloat16* sAl = base + G_A_ELT;
        __nv_bfloat16* sBh = base + 2 * G_A_ELT;
        __nv_bfloat16* sBl = base + 2 * G_A_ELT + G_B_ELT;
        #pragma unroll
        for (int i = 0; i < 2; i++) {
            int idx = tid + i * 256;              // 0..511
            int row = idx >> 2;
            int c   = (idx & 3) * 8;
            const size_t ga = (size_t)(bm + row) * K + k0 + c;
            cp_async16(smem_u32(sAh + row * ASTR + c), Ahg + ga);
            cp_async16(smem_u32(sAl + row * ASTR + c), Alg + ga);
        }
        #pragma unroll
        for (int i = 0; i < 2; i++) {
            int idx = tid + i * 256;
            int row = idx >> 4;
            int c   = (idx & 15) * 8;
            const size_t gb = (size_t)(k0 + row) * N + bn + c;
            cp_async16(smem_u32(sBh + row * BSTR + c), Bhg + gb);
            cp_async16(smem_u32(sBl + row * BSTR + c), Blg + gb);
        }
    };

    const int nk = K / GBK;   // 32
    prefetch(0, 0); cp_commit();
    prefetch(GBK, 1); cp_commit();

    for (int kt = 0; kt < nk; kt++) {
        cp_wait<1>();
        __syncthreads();
        const int s = kt & 1;
        __nv_bfloat16* base = dsm + s * G_STAGE;
        __nv_bfloat16* sAh = base;
        __nv_bfloat16* sAl = base + G_A_ELT;
        __nv_bfloat16* sBh = base + 2 * G_A_ELT;
        __nv_bfloat16* sBl = base + 2 * G_A_ELT + G_B_ELT;

        #pragma unroll
        for (int ks = 0; ks < 2; ks++) {
            uint32_t ah[4][4], al[4][4], bh[4][2], bl[4][2];
            #pragma unroll
            for (int i = 0; i < 4; i++) {
                uint32_t ad = smem_u32(sAh + (wm + i * 16 + lm_r) * ASTR + ks * 16 + lm_c);
                ldsm_x4(ad, ah[i][0], ah[i][1], ah[i][2], ah[i][3]);
                uint32_t ad2 = smem_u32(sAl + (wm + i * 16 + lm_r) * ASTR + ks * 16 + lm_c);
                ldsm_x4(ad2, al[i][0], al[i][1], al[i][2], al[i][3]);
            }
            #pragma unroll
            for (int j2 = 0; j2 < 2; j2++) {
                uint32_t bd = smem_u32(sBh + (ks * 16 + lm_r) * BSTR + wn + j2 * 16 + lm_c);
                ldsm_x4_t(bd, bh[2 * j2][0], bh[2 * j2][1], bh[2 * j2 + 1][0], bh[2 * j2 + 1][1]);
                uint32_t bd2 = smem_u32(sBl + (ks * 16 + lm_r) * BSTR + wn + j2 * 16 + lm_c);
                ldsm_x4_t(bd2, bl[2 * j2][0], bl[2 * j2][1], bl[2 * j2 + 1][0], bl[2 * j2 + 1][1]);
            }
            #pragma unroll
            for (int i = 0; i < 4; i++)
                #pragma unroll
                for (int j = 0; j < 4; j++) mma16816(acc[i][j], ah[i], bh[j]);
            #pragma unroll
            for (int i = 0; i < 4; i++)
                #pragma unroll
                for (int j = 0; j < 4; j++) mma16816(acc[i][j], ah[i], bl[j]);
            #pragma unroll
            for (int i = 0; i < 4; i++)
                #pragma unroll
                for (int j = 0; j < 4; j++) mma16816(acc[i][j], al[i], bh[j]);
        }
        __syncthreads();
        if (kt + 2 < nk) prefetch((kt + 2) * GBK, s);
        cp_commit();
    }

    // Epilogue
    #pragma unroll
    for (int i = 0; i < 4; i++) {
        int r0 = bm + wm + i * 16 + g;
        #pragma unroll
        for (int j = 0; j < 4; j++) {
            int c = bn + wn + j * 8 + tig * 2;
            float b0 = bias[c], b1 = bias[c + 1];
            float x0 = acc[i][j][0] + b0, y0 = acc[i][j][1] + b1;
            float x1 = acc[i][j][2] + b0, y1 = acc[i][j][3] + b1;
            if (SPLIT_OUT) {
                uint32_t h0, l0, h1, l1;
                split_pack(x0, y0, h0, l0);
                split_pack(x1, y1, h1, l1);
                *(uint32_t*)&Chg[(size_t)r0 * N + c]       = h0;
                *(uint32_t*)&Clg[(size_t)r0 * N + c]       = l0;
                *(uint32_t*)&Chg[(size_t)(r0 + 8) * N + c] = h1;
                *(uint32_t*)&Clg[(size_t)(r0 + 8) * N + c] = l1;
            } else {
                *(float2*)&C[(size_t)r0 * N + c]       = make_float2(x0, y0);
                *(float2*)&C[(size_t)(r0 + 8) * N + c] = make_float2(x1, y1);
            }
        }
    }
}

// ---------------------------------------------------------------------------
// Flash attention on pre-split bf16. CTA: 128 q-rows of one (b,h), 8 warps.
// K/V tiles (64 keys) double-buffered via cp.async. Q frags direct from global.
// ---------------------------------------------------------------------------
#define QBLK 128
#define KBLK 64
#define KSTR 72
#define A_ARR (KBLK * KSTR)            // 4608 elts per array
#define A_STAGE (4 * A_ARR)            // Kh,Kl,Vh,Vl = 18432 elts
#define A_SMEM_BYTES (2 * A_STAGE * 2) // 73728 B

__global__ __launch_bounds__(256)
void attn_tc(const __nv_bfloat16* __restrict__ Qhg, const __nv_bfloat16* __restrict__ Qlg,
             const __nv_bfloat16* __restrict__ Khg, const __nv_bfloat16* __restrict__ Klg,
             const __nv_bfloat16* __restrict__ Vhg, const __nv_bfloat16* __restrict__ Vlg,
             __nv_bfloat16* __restrict__ Ohg, __nv_bfloat16* __restrict__ Olg)
{
    extern __shared__ __align__(16) __nv_bfloat16 dsm[];

    const int tid  = threadIdx.x;
    const int lane = tid & 31;
    const int warp = tid >> 5;
    const int g    = lane >> 2;
    const int tig  = lane & 3;
    const int lm_r = (lane & 7) + ((lane >> 3) & 1) * 8;
    const int lm_c = (lane >> 4) * 8;

    const int b  = blockIdx.z;
    const int h  = blockIdx.y;
    const int q0 = blockIdx.x * QBLK;

    // ---- Q fragments straight from global (held all kernel) ----
    uint32_t qh[4][4], ql[4][4];
    {
        const int qrow = q0 + warp * 16 + g;
        const size_t qb = ((size_t)(b * SEQ + qrow)) * D_MODEL + h * DHEAD;
        #pragma unroll
        for (int ks = 0; ks < 4; ks++) {
            const int c = ks * 16 + tig * 2;
            qh[ks][0] = *(const uint32_t*)&Qhg[qb + c];
            qh[ks][1] = *(const uint32_t*)&Qhg[qb + 8 * D_MODEL + c];
            qh[ks][2] = *(const uint32_t*)&Qhg[qb + c + 8];
            qh[ks][3] = *(const uint32_t*)&Qhg[qb + 8 * D_MODEL + c + 8];
            ql[ks][0] = *(const uint32_t*)&Qlg[qb + c];
            ql[ks][1] = *(const uint32_t*)&Qlg[qb + 8 * D_MODEL + c];
            ql[ks][2] = *(const uint32_t*)&Qlg[qb + c + 8];
            ql[ks][3] = *(const uint32_t*)&Qlg[qb + 8 * D_MODEL + c + 8];
        }
    }

    auto prefetch = [&](int kt, int s) {
        __nv_bfloat16* base = dsm + s * A_STAGE;
        const size_t gk = ((size_t)(b * SEQ + kt * KBLK)) * D_MODEL + h * DHEAD;
        const __nv_bfloat16* srcs[4] = {Khg, Klg, Vhg, Vlg};
        #pragma unroll
        for (int i = 0; i < 8; i++) {
            int idx = tid + i * 256;          // 0..2047
            int arr = idx >> 9;               // 0..3
            int rem = idx & 511;
            int row = rem >> 3;               // 0..63
            int c   = (rem & 7) * 8;          // 0..56
            cp_async16(smem_u32(base + arr * A_ARR + row * KSTR + c),
                       srcs[arr] + gk + (size_t)row * D_MODEL + c);
        }
    };

    float out[8][4];
    #pragma unroll
    for (int j = 0; j < 8; j++)
        #pragma unroll
        for (int t = 0; t < 4; t++) out[j][t] = 0.0f;
    float mrow[2] = {-INFINITY, -INFINITY};
    float lrow[2] = {0.0f, 0.0f};

    const int nk = SEQ / KBLK;   // 16
    prefetch(0, 0); cp_commit();
    prefetch(1, 1); cp_commit();

    for (int kt = 0; kt < nk; kt++) {
        cp_wait<1>();
        __syncthreads();
        const int s = kt & 1;
        __nv_bfloat16* base = dsm + s * A_STAGE;
        __nv_bfloat16* sKh = base;
        __nv_bfloat16* sKl = base + A_ARR;
        __nv_bfloat16* sVh = base + 2 * A_ARR;
        __nv_bfloat16* sVl = base + 3 * A_ARR;

        // ---- QK^T ----
        float sc[8][4];
        #pragma unroll
        for (int j = 0; j < 8; j++)
            #pragma unroll
            for (int t = 0; t < 4; t++) sc[j][t] = 0.0f;

        #pragma unroll
        for (int ks = 0; ks < 4; ks++) {
            uint32_t bh[8][2], bl[8][2];
            const int dd = ks * 16 + tig * 2;
            #pragma unroll
            for (int j = 0; j < 8; j++) {
                int key = j * 8 + g;
                bh[j][0] = *(const uint32_t*)(sKh + key * KSTR + dd);
                bh[j][1] = *(const uint32_t*)(sKh + key * KSTR + dd + 8);
                bl[j][0] = *(const uint32_t*)(sKl + key * KSTR + dd);
                bl[j][1] = *(const uint32_t*)(sKl + key * KSTR + dd + 8);
            }
            #pragma unroll
            for (int j = 0; j < 8; j++) mma16816(sc[j], qh[ks], bh[j]);
            #pragma unroll
            for (int j = 0; j < 8; j++) mma16816(sc[j], qh[ks], bl[j]);
            #pragma unroll
            for (int j = 0; j < 8; j++) mma16816(sc[j], ql[ks], bh[j]);
        }
        #pragma unroll
        for (int j = 0; j < 8; j++)
            #pragma unroll
            for (int t = 0; t < 4; t++) sc[j][t] *= 0.125f;   // 1/sqrt(64)

        // ---- online softmax (2 rows per thread) ----
        #pragma unroll
        for (int r = 0; r < 2; r++) {
            float mx = -INFINITY;
            #pragma unroll
            for (int j = 0; j < 8; j++) {
                mx = fmaxf(mx, sc[j][2 * r]);
                mx = fmaxf(mx, sc[j][2 * r + 1]);
            }
            mx = fmaxf(mx, __shfl_xor_sync(0xFFFFFFFFu, mx, 1));
            mx = fmaxf(mx, __shfl_xor_sync(0xFFFFFFFFu, mx, 2));
            float newm = fmaxf(mrow[r], mx);
            float corr = __expf(mrow[r] - newm);
            mrow[r] = newm;
            float lsum = 0.0f;
            #pragma unroll
            for (int j = 0; j < 8; j++) {
                float e0 = __expf(sc[j][2 * r]     - newm);
                float e1 = __expf(sc[j][2 * r + 1] - newm);
                sc[j][2 * r] = e0; sc[j][2 * r + 1] = e1;
                lsum += e0 + e1;
                out[j][2 * r]     *= corr;
                out[j][2 * r + 1] *= corr;
            }
            lrow[r] = lrow[r] * corr + lsum;
        }

        // ---- P @ V ----
        #pragma unroll
        for (int ss = 0; ss < 4; ss++) {
            uint32_t ph[4], pl[4];
            split_pack(sc[2 * ss][0],     sc[2 * ss][1],     ph[0], pl[0]);
            split_pack(sc[2 * ss][2],     sc[2 * ss][3],     ph[1], pl[1]);
            split_pack(sc[2 * ss + 1][0], sc[2 * ss + 1][1], ph[2], pl[2]);
            split_pack(sc[2 * ss + 1][2], sc[2 * ss + 1][3], ph[3], pl[3]);

            uint32_t vh[8][2], vl[8][2];
            #pragma unroll
            for (int j2 = 0; j2 < 4; j2++) {
                int row = ss * 16 + lm_r;
                int col = j2 * 16 + lm_c;
                uint32_t vd = smem_u32(sVh + row * KSTR + col);
                ldsm_x4_t(vd, vh[2 * j2][0], vh[2 * j2][1], vh[2 * j2 + 1][0], vh[2 * j2 + 1][1]);
                uint32_t vd2 = smem_u32(sVl + row * KSTR + col);
                ldsm_x4_t(vd2, vl[2 * j2][0], vl[2 * j2][1], vl[2 * j2 + 1][0], vl[2 * j2 + 1][1]);
            }
            #pragma unroll
            for (int j = 0; j < 8; j++) mma16816(out[j], ph, vh[j]);
            #pragma unroll
            for (int j = 0; j < 8; j++) mma16816(out[j], ph, vl[j]);
            #pragma unroll
            for (int j = 0; j < 8; j++) mma16816(out[j], pl, vh[j]);
        }
        __syncthreads();
        if (kt + 2 < nk) prefetch(kt + 2, s);
        cp_commit();
    }

    // ---- finalize: l reduction, normalize, split, store ----
    #pragma unroll
    for (int r = 0; r < 2; r++) {
        lrow[r] += __shfl_xor_sync(0xFFFFFFFFu, lrow[r], 1);
        lrow[r] += __shfl_xor_sync(0xFFFFFFFFu, lrow[r], 2);
    }
    const float inv0 = 1.0f / lrow[0];
    const float inv1 = 1.0f / lrow[1];
    const int row0 = q0 + warp * 16 + g;
    #pragma unroll
    for (int j = 0; j < 8; j++) {
        int d = j * 8 + tig * 2;
        size_t addr = ((size_t)(b * SEQ + row0)) * D_MODEL + h * DHEAD + d;
        uint32_t h0, l0, h1, l1;
        split_pack(out[j][0] * inv0, out[j][1] * inv0, h0, l0);
        split_pack(out[j][2] * inv1, out[j][3] * inv1, h1, l1);
        *(uint32_t*)&Ohg[addr]                 = h0;
        *(uint32_t*)&Olg[addr]                 = l0;
        *(uint32_t*)&Ohg[addr + 8 * D_MODEL]   = h1;
        *(uint32_t*)&Olg[addr + 8 * D_MODEL]   = l1;
    }
}

// ---------------------------------------------------------------------------
// Launch
// ---------------------------------------------------------------------------
extern "C" void kernel_launch(void* const* d_in, const int* in_sizes, int n_in,
                              void* d_out, int out_size)
{
    const float* queries = (const float*)d_in[0];
    const float* keys    = (const float*)d_in[1];
    const float* values  = (const float*)d_in[2];
    const float* Wq      = (const float*)d_in[3];
    const float* bq      = (const float*)d_in[4];
    const float* Wk      = (const float*)d_in[5];
    const float* bk      = (const float*)d_in[6];
    const float* Wv      = (const float*)d_in[7];
    const float* bv      = (const float*)d_in[8];
    const float* Wo      = (const float*)d_in[9];
    const float* bo      = (const float*)d_in[10];
    float* out = (float*)d_out;

    // Resolve scratch symbols
    __nv_bfloat16 *xq_h, *xq_l, *xk_h, *xk_l, *xv_h, *xv_l;
    __nv_bfloat16 *wq_h, *wq_l, *wk_h, *wk_l, *wv_h, *wv_l, *wo_h, *wo_l;
    __nv_bfloat16 *q_h, *q_l, *k_h, *k_l, *v_h, *v_l, *o_h, *o_l;
    cudaGetSymbolAddress((void**)&xq_h, g_xq_h); cudaGetSymbolAddress((void**)&xq_l, g_xq_l);
    cudaGetSymbolAddress((void**)&xk_h, g_xk_h); cudaGetSymbolAddress((void**)&xk_l, g_xk_l);
    cudaGetSymbolAddress((void**)&xv_h, g_xv_h); cudaGetSymbolAddress((void**)&xv_l, g_xv_l);
    cudaGetSymbolAddress((void**)&wq_h, g_wq_h); cudaGetSymbolAddress((void**)&wq_l, g_wq_l);
    cudaGetSymbolAddress((void**)&wk_h, g_wk_h); cudaGetSymbolAddress((void**)&wk_l, g_wk_l);
    cudaGetSymbolAddress((void**)&wv_h, g_wv_h); cudaGetSymbolAddress((void**)&wv_l, g_wv_l);
    cudaGetSymbolAddress((void**)&wo_h, g_wo_h); cudaGetSymbolAddress((void**)&wo_l, g_wo_l);
    cudaGetSymbolAddress((void**)&q_h,  g_q_h);  cudaGetSymbolAddress((void**)&q_l,  g_q_l);
    cudaGetSymbolAddress((void**)&k_h,  g_k_h);  cudaGetSymbolAddress((void**)&k_l,  g_k_l);
    cudaGetSymbolAddress((void**)&v_h,  g_v_h);  cudaGetSymbolAddress((void**)&v_l,  g_v_l);
    cudaGetSymbolAddress((void**)&o_h,  g_o_h);  cudaGetSymbolAddress((void**)&o_l,  g_o_l);

    // Opt-in to >48KB dynamic smem (idempotent attribute set, not an allocation)
    cudaFuncSetAttribute(gemm_tc<true>,  cudaFuncAttributeMaxDynamicSharedMemorySize, G_SMEM_BYTES);
    cudaFuncSetAttribute(gemm_tc<false>, cudaFuncAttributeMaxDynamicSharedMemorySize, G_SMEM_BYTES);
    cudaFuncSetAttribute(attn_tc,        cudaFuncAttributeMaxDynamicSharedMemorySize, A_SMEM_BYTES);

    // 1) split inputs + weights
    const int act4 = (int)(NACT / 4), w4 = (int)(NW / 4);
    split_kernel<<<act4 / 256, 256>>>(queries, xq_h, xq_l, act4);
    split_kernel<<<act4 / 256, 256>>>(keys,    xk_h, xk_l, act4);
    split_kernel<<<act4 / 256, 256>>>(values,  xv_h, xv_l, act4);
    split_kernel<<<w4 / 256, 256>>>(Wq, wq_h, wq_l, w4);
    split_kernel<<<w4 / 256, 256>>>(Wk, wk_h, wk_l, w4);
    split_kernel<<<w4 / 256, 256>>>(Wv, wv_h, wv_l, w4);
    split_kernel<<<w4 / 256, 256>>>(Wo, wo_h, wo_l, w4);

    // 2) projections (split bf16 out)
    const dim3 gg(D_MODEL / GBN, MROWS / GBM);
    gemm_tc<true><<<gg, 256, G_SMEM_BYTES>>>(xq_h, xq_l, wq_h, wq_l, bq,
                                             nullptr, q_h, q_l, MROWS, D_MODEL, D_MODEL);
    gemm_tc<true><<<gg, 256, G_SMEM_BYTES>>>(xk_h, xk_l, wk_h, wk_l, bk,
                                             nullptr, k_h, k_l, MROWS, D_MODEL, D_MODEL);
    gemm_tc<true><<<gg, 256, G_SMEM_BYTES>>>(xv_h, xv_l, wv_h, wv_l, bv,
                                             nullptr, v_h, v_l, MROWS, D_MODEL, D_MODEL);

    // 3) attention
    attn_tc<<<dim3(SEQ / QBLK, NH, BATCH), 256, A_SMEM_BYTES>>>(
        q_h, q_l, k_h, k_l, v_h, v_l, o_h, o_l);

    // 4) output projection (fp32 out)
    gemm_tc<false><<<gg, 256, G_SMEM_BYTES>>>(o_h, o_l, wo_h, wo_l, bo,
                                              out, nullptr, nullptr, MROWS, D_MODEL, D_MODEL);
}

// round 5
// speedup vs baseline: 1.0182x; 1.0182x over previous
#include <cuda_runtime.h>
#include <cuda_fp16.h>
#include <math.h>
#include <stdint.h>

#define D_MODEL 1024
#define NH      16
#define DHEAD   64
#define BATCH   4
#define SEQ     1024
#define MROWS   (BATCH * SEQ)   // 4096

// ---------------------------------------------------------------------------
// Scratch (static device globals). fp16.
// ---------------------------------------------------------------------------
#define NACT ((size_t)MROWS * D_MODEL)   // 4M
#define NW   ((size_t)D_MODEL * D_MODEL) // 1M
__device__ __half g_wq[NW], g_wk[NW], g_wv[NW], g_wo[NW];  // [K,N] fp16 rounded
__device__ __half g_qh[NACT], g_ql[NACT];   // Q split (mma 'a' operand)
__device__ __half g_kh[NACT];               // K single fp16 ('b' operand)
__device__ __half g_vh[NACT];               // V single fp16 ('b' operand)
__device__ __half g_oh[NACT], g_ol[NACT];   // attn out split ('a' for out proj)

// ---------------------------------------------------------------------------
// Helpers
// ---------------------------------------------------------------------------
__device__ __forceinline__ uint32_t smem_u32(const void* p) {
    return (uint32_t)__cvta_generic_to_shared(p);
}
__device__ __forceinline__ void cp_async16(uint32_t dst, const void* src) {
    asm volatile("cp.async.cg.shared.global [%0], [%1], 16;" :: "r"(dst), "l"(src));
}
__device__ __forceinline__ void cp_commit() {
    asm volatile("cp.async.commit_group;");
}
template <int N>
__device__ __forceinline__ void cp_wait() {
    asm volatile("cp.async.wait_group %0;" :: "n"(N));
}
__device__ __forceinline__ void ldsm_x4(uint32_t addr, uint32_t& r0, uint32_t& r1,
                                        uint32_t& r2, uint32_t& r3) {
    asm volatile("ldmatrix.sync.aligned.m8n8.x4.shared.b16 {%0,%1,%2,%3}, [%4];"
                 : "=r"(r0), "=r"(r1), "=r"(r2), "=r"(r3) : "r"(addr));
}
__device__ __forceinline__ void ldsm_x4_t(uint32_t addr, uint32_t& r0, uint32_t& r1,
                                          uint32_t& r2, uint32_t& r3) {
    asm volatile("ldmatrix.sync.aligned.m8n8.x4.trans.shared.b16 {%0,%1,%2,%3}, [%4];"
                 : "=r"(r0), "=r"(r1), "=r"(r2), "=r"(r3) : "r"(addr));
}
__device__ __forceinline__ void mma_h(float c[4], const uint32_t a[4], const uint32_t b[2]) {
    asm volatile(
        "mma.sync.aligned.m16n8k16.row.col.f32.f16.f16.f32 "
        "{%0,%1,%2,%3}, {%4,%5,%6,%7}, {%8,%9}, {%0,%1,%2,%3};"
        : "+f"(c[0]), "+f"(c[1]), "+f"(c[2]), "+f"(c[3])
        : "r"(a[0]), "r"(a[1]), "r"(a[2]), "r"(a[3]), "r"(b[0]), "r"(b[1]));
}
// fp32 pair -> packed fp16 hi + packed fp16 residual
__device__ __forceinline__ void split_pack_h(float x, float y, uint32_t& hi, uint32_t& lo) {
    __half xh = __float2half_rn(x);
    __half yh = __float2half_rn(y);
    __half2 h2; h2.x = xh; h2.y = yh;
    hi = *reinterpret_cast<uint32_t*>(&h2);
    float xl = x - __half2float(xh);
    float yl = y - __half2float(yh);
    __half2 l2 = __floats2half2_rn(xl, yl);
    lo = *reinterpret_cast<uint32_t*>(&l2);
}
__device__ __forceinline__ uint32_t pack_h(float x, float y) {
    __half2 h2; h2.x = __float2half_rn(x); h2.y = __float2half_rn(y);
    return *reinterpret_cast<uint32_t*>(&h2);
}

// ---------------------------------------------------------------------------
// Weight rounding: 4 weights [K,N] fp32 -> fp16, one launch (blockIdx.y = which)
// ---------------------------------------------------------------------------
__global__ __launch_bounds__(256)
void round_w4(const float* __restrict__ w0, const float* __restrict__ w1,
              const float* __restrict__ w2, const float* __restrict__ w3,
              __half* __restrict__ o0, __half* __restrict__ o1,
              __half* __restrict__ o2, __half* __restrict__ o3)
{
    const float* src = (blockIdx.y == 0) ? w0 : (blockIdx.y == 1) ? w1
                     : (blockIdx.y == 2) ? w2 : w3;
    __half* dst = (blockIdx.y == 0) ? o0 : (blockIdx.y == 1) ? o1
                : (blockIdx.y == 2) ? o2 : o3;
    size_t i = ((size_t)blockIdx.x * 256 + threadIdx.x) * 8;
    float4 a = *(const float4*)&src[i];
    float4 b = *(const float4*)&src[i + 4];
    uint4 o;
    o.x = pack_h(a.x, a.y); o.y = pack_h(a.z, a.w);
    o.z = pack_h(b.x, b.y); o.w = pack_h(b.z, b.w);
    *(uint4*)&dst[i] = o;
}

// ---------------------------------------------------------------------------
// GEMM: C[M,N] = A @ W + bias.  A = fp32 (split in-kernel) or fp16 presplit.
// W = fp16 [K,N]. 128x128x32 tiles, 8 warps (64x32 warp tile), 2-stage cp.async.
// OUT: 0 = fp32 C;  1 = fp16 hi only;  2 = fp16 hi + lo.
// ---------------------------------------------------------------------------
#define GBK  32
#define ASTR 40     // fp16 elems per A smem row
#define BSTR 136    // fp16 elems per B smem row
#define AH_ELT (128 * ASTR)              // 5120
#define B_ELT  (GBK * BSTR)              // 4352
#define G_STAGE (2 * AH_ELT + B_ELT)     // Ah + Al + Bh = 14592 halfs
#define G_SMEM (2 * G_STAGE * 2)         // 58368 B
#define G_NK   (D_MODEL / GBK)           // 32

template <bool ASP, int OUT>
__global__ __launch_bounds__(256)
void gemm_h(const float* __restrict__ Af,
            const __half* __restrict__ Ahg, const __half* __restrict__ Alg,
            const __half* __restrict__ Bg, const float* __restrict__ bias,
            float* __restrict__ Cf, __half* __restrict__ Ch, __half* __restrict__ Cl)
{
    extern __shared__ __align__(16) __half dsm[];

    const int tid  = threadIdx.x;
    const int lane = tid & 31;
    const int warp = tid >> 5;
    const int g    = lane >> 2;
    const int tig  = lane & 3;
    const int wm   = (warp >> 2) * 64;
    const int wn   = (warp & 3) * 32;
    const int bm   = blockIdx.y * 128;
    const int bn   = blockIdx.x * 128;
    const int lm_r = (lane & 7) + ((lane >> 3) & 1) * 8;
    const int lm_c = (lane >> 4) * 8;

    float acc[4][4][4];
    #pragma unroll
    for (int i = 0; i < 4; i++)
        #pragma unroll
        for (int j = 0; j < 4; j++)
            #pragma unroll
            for (int t = 0; t < 4; t++) acc[i][j][t] = 0.0f;

    // ---- loaders ----
    // B tile: 32 rows x 128 halfs = 16 chunks/row -> 512 chunks, 2/thread
    auto load_B = [&](int kt, int s) {
        __half* sB = dsm + s * G_STAGE + 2 * AH_ELT;
        #pragma unroll
        for (int i = 0; i < 2; i++) {
            int idx = tid + i * 256;
            int row = idx >> 4;
            int c   = (idx & 15) * 8;
            cp_async16(smem_u32(sB + row * BSTR + c),
                       Bg + (size_t)(kt * GBK + row) * D_MODEL + bn + c);
        }
    };
    // A presplit: 128 rows x 4 chunks x 2 arrays = 1024 chunks, 4/thread
    auto load_A_presplit = [&](int kt, int s) {
        __half* base = dsm + s * G_STAGE;
        #pragma unroll
        for (int i = 0; i < 4; i++) {
            int idx = tid + i * 256;
            int arr = idx >> 9;
            int rem = idx & 511;
            int row = rem >> 2;
            int c   = (rem & 3) * 8;
            const __half* src = arr ? Alg : Ahg;
            cp_async16(smem_u32(base + arr * AH_ELT + row * ASTR + c),
                       src + (size_t)(bm + row) * D_MODEL + kt * GBK + c);
        }
    };
    // A fp32: 4 float4 per thread into regs
    auto ldg_A = [&](int kt, float4* r) {
        #pragma unroll
        for (int i = 0; i < 4; i++) {
            int p   = tid + i * 256;         // 0..1023
            int row = p >> 3;
            int kk  = (p & 7) * 4;
            r[i] = *(const float4*)&Af[(size_t)(bm + row) * D_MODEL + kt * GBK + kk];
        }
    };
    auto sts_A_split = [&](const float4* r, int s) {
        __half* sAh = dsm + s * G_STAGE;
        __half* sAl = sAh + AH_ELT;
        #pragma unroll
        for (int i = 0; i < 4; i++) {
            int p   = tid + i * 256;
            int row = p >> 3;
            int kk  = (p & 7) * 4;
            uint32_t h0, l0, h1, l1;
            split_pack_h(r[i].x, r[i].y, h0, l0);
            split_pack_h(r[i].z, r[i].w, h1, l1);
            *(uint2*)&sAh[row * ASTR + kk] = make_uint2(h0, h1);
            *(uint2*)&sAl[row * ASTR + kk] = make_uint2(l0, l1);
        }
    };

    // ---- prologue ----
    float4 rA0[4], rA1[4];
    if (ASP) {
        load_A_presplit(0, 0); load_B(0, 0); cp_commit();
        load_A_presplit(1, 1); load_B(1, 1); cp_commit();
    } else {
        ldg_A(0, rA0); ldg_A(1, rA1);
        load_B(0, 0); cp_commit();
        load_B(1, 1); cp_commit();
        sts_A_split(rA0, 0);
        ldg_A(2, rA0);
    }
    cp_wait<1>();
    __syncthreads();

    for (int kt = 0; kt < G_NK; kt++) {
        const int s = kt & 1;
        __half* sAh = dsm + s * G_STAGE;
        __half* sAl = sAh + AH_ELT;
        __half* sB  = sAh + 2 * AH_ELT;

        if (!ASP) {
            // STS A(kt+1) into other stage (safe: last read at kt-1, synced)
            if (kt + 1 < G_NK) sts_A_split(((kt + 1) & 1) ? rA1 : rA0, s ^ 1);
            if (kt + 3 < G_NK) ldg_A(kt + 3, ((kt + 1) & 1) ? rA1 : rA0);
        }

        #pragma unroll
        for (int ks = 0; ks < 2; ks++) {
            uint32_t ah[4][4], al[4][4], bh[4][2];
            #pragma unroll
            for (int i = 0; i < 4; i++) {
                uint32_t ad = smem_u32(sAh + (wm + i * 16 + lm_r) * ASTR + ks * 16 + lm_c);
                ldsm_x4(ad, ah[i][0], ah[i][1], ah[i][2], ah[i][3]);
                uint32_t ad2 = smem_u32(sAl + (wm + i * 16 + lm_r) * ASTR + ks * 16 + lm_c);
                ldsm_x4(ad2, al[i][0], al[i][1], al[i][2], al[i][3]);
            }
            #pragma unroll
            for (int j2 = 0; j2 < 2; j2++) {
                uint32_t bd = smem_u32(sB + (ks * 16 + lm_r) * BSTR + wn + j2 * 16 + lm_c);
                ldsm_x4_t(bd, bh[2 * j2][0], bh[2 * j2][1], bh[2 * j2 + 1][0], bh[2 * j2 + 1][1]);
            }
            #pragma unroll
            for (int i = 0; i < 4; i++)
                #pragma unroll
                for (int j = 0; j < 4; j++) mma_h(acc[i][j], ah[i], bh[j]);
            #pragma unroll
            for (int i = 0; i < 4; i++)
                #pragma unroll
                for (int j = 0; j < 4; j++) mma_h(acc[i][j], al[i], bh[j]);
        }
        __syncthreads();
        if (kt + 2 < G_NK) {
            if (ASP) load_A_presplit(kt + 2, s);
            load_B(kt + 2, s);
        }
        cp_commit();
        cp_wait<1>();
        __syncthreads();
    }

    // ---- epilogue ----
    #pragma unroll
    for (int i = 0; i < 4; i++) {
        int r0 = bm + wm + i * 16 + g;
        #pragma unroll
        for (int j = 0; j < 4; j++) {
            int c = bn + wn + j * 8 + tig * 2;
            float b0 = bias[c], b1 = bias[c + 1];
            float x0 = acc[i][j][0] + b0, y0 = acc[i][j][1] + b1;
            float x1 = acc[i][j][2] + b0, y1 = acc[i][j][3] + b1;
            if (OUT == 0) {
                *(float2*)&Cf[(size_t)r0 * D_MODEL + c]       = make_float2(x0, y0);
                *(float2*)&Cf[(size_t)(r0 + 8) * D_MODEL + c] = make_float2(x1, y1);
            } else if (OUT == 1) {
                *(uint32_t*)&Ch[(size_t)r0 * D_MODEL + c]       = pack_h(x0, y0);
                *(uint32_t*)&Ch[(size_t)(r0 + 8) * D_MODEL + c] = pack_h(x1, y1);
            } else {
                uint32_t h0, l0, h1, l1;
                split_pack_h(x0, y0, h0, l0);
                split_pack_h(x1, y1, h1, l1);
                *(uint32_t*)&Ch[(size_t)r0 * D_MODEL + c]       = h0;
                *(uint32_t*)&Cl[(size_t)r0 * D_MODEL + c]       = l0;
                *(uint32_t*)&Ch[(size_t)(r0 + 8) * D_MODEL + c] = h1;
                *(uint32_t*)&Cl[(size_t)(r0 + 8) * D_MODEL + c] = l1;
            }
        }
    }
}

// ---------------------------------------------------------------------------
// Flash attention, fp16. CTA: 128 q-rows of one (b,h), 8 warps.
// K/V single fp16 tiles (64 keys) double-buffered cp.async. Q hi+lo frags.
// ---------------------------------------------------------------------------
#define QBLK 128
#define KBLK 64
#define KSTR 72
#define KV_ARR (KBLK * KSTR)          // 4608 halfs
#define KV_STAGE (2 * KV_ARR)         // Kh + Vh = 9216 halfs
#define A_SMEM (2 * KV_STAGE * 2)     // 36864 B (also exactly fits Q staging)
#define A_NK (SEQ / KBLK)             // 16

__global__ __launch_bounds__(256)
void attn_h(const __half* __restrict__ Qhg, const __half* __restrict__ Qlg,
            const __half* __restrict__ Khg, const __half* __restrict__ Vhg,
            __half* __restrict__ Ohg, __half* __restrict__ Olg)
{
    extern __shared__ __align__(16) __half dsm[];

    const int tid  = threadIdx.x;
    const int lane = tid & 31;
    const int warp = tid >> 5;
    const int g    = lane >> 2;
    const int tig  = lane & 3;
    const int lm_r = (lane & 7) + ((lane >> 3) & 1) * 8;
    const int lm_c = (lane >> 4) * 8;

    const int b  = blockIdx.z;
    const int h  = blockIdx.y;
    const int q0 = blockIdx.x * QBLK;
    const size_t qbase = ((size_t)(b * SEQ + q0)) * D_MODEL + h * DHEAD;

    // ---- Q staging (coalesced) then fragments; smem reused for K/V after ----
    {
        // sQh = dsm[0..9216), sQl = dsm[9216..18432); row stride 72
        #pragma unroll
        for (int i = 0; i < 8; i++) {
            int idx = tid + i * 256;          // 0..2047
            int arr = idx >> 10;              // 0: hi, 1: lo
            int rem = idx & 1023;
            int row = rem >> 3;               // 0..127
            int c   = (rem & 7) * 8;          // 0..56
            const __half* src = arr ? Qlg : Qhg;
            *(uint4*)&dsm[arr * 9216 + row * KSTR + c] =
                *(const uint4*)&src[qbase + (size_t)row * D_MODEL + c];
        }
    }
    __syncthreads();
    uint32_t qh[4][4], ql[4][4];
    #pragma unroll
    for (int ks = 0; ks < 4; ks++) {
        uint32_t ad = smem_u32(&dsm[(warp * 16 + lm_r) * KSTR + ks * 16 + lm_c]);
        ldsm_x4(ad, qh[ks][0], qh[ks][1], qh[ks][2], qh[ks][3]);
        uint32_t ad2 = smem_u32(&dsm[9216 + (warp * 16 + lm_r) * KSTR + ks * 16 + lm_c]);
        ldsm_x4(ad2, ql[ks][0], ql[ks][1], ql[ks][2], ql[ks][3]);
    }
    __syncthreads();   // smem now free for K/V stages

    auto prefetch = [&](int kt, int s) {
        __half* base = dsm + s * KV_STAGE;
        const size_t gk = ((size_t)(b * SEQ + kt * KBLK)) * D_MODEL + h * DHEAD;
        #pragma unroll
        for (int i = 0; i < 4; i++) {
            int idx = tid + i * 256;          // 0..1023
            int arr = idx >> 9;               // 0: K, 1: V
            int rem = idx & 511;
            int row = rem >> 3;               // 0..63
            int c   = (rem & 7) * 8;
            const __half* src = arr ? Vhg : Khg;
            cp_async16(smem_u32(base + arr * KV_ARR + row * KSTR + c),
                       src + gk + (size_t)row * D_MODEL + c);
        }
    };

    float out[8][4];
    #pragma unroll
    for (int j = 0; j < 8; j++)
        #pragma unroll
        for (int t = 0; t < 4; t++) out[j][t] = 0.0f;
    float mrow[2] = {-INFINITY, -INFINITY};
    float lrow[2] = {0.0f, 0.0f};

    prefetch(0, 0); cp_commit();
    prefetch(1, 1); cp_commit();
    cp_wait<1>();
    __syncthreads();

    for (int kt = 0; kt < A_NK; kt++) {
        const int s = kt & 1;
        __half* sK = dsm + s * KV_STAGE;
        __half* sV = sK + KV_ARR;

        // ---- QK^T (2 passes: qh.kh + ql.kh) ----
        float sc[8][4];
        #pragma unroll
        for (int j = 0; j < 8; j++)
            #pragma unroll
            for (int t = 0; t < 4; t++) sc[j][t] = 0.0f;

        #pragma unroll
        for (int ks = 0; ks < 4; ks++) {
            uint32_t bh[8][2];
            const int dd = ks * 16 + tig * 2;
            #pragma unroll
            for (int j = 0; j < 8; j++) {
                int key = j * 8 + g;
                bh[j][0] = *(const uint32_t*)(sK + key * KSTR + dd);
                bh[j][1] = *(const uint32_t*)(sK + key * KSTR + dd + 8);
            }
            #pragma unroll
            for (int j = 0; j < 8; j++) mma_h(sc[j], qh[ks], bh[j]);
            #pragma unroll
            for (int j = 0; j < 8; j++) mma_h(sc[j], ql[ks], bh[j]);
        }
        #pragma unroll
        for (int j = 0; j < 8; j++)
            #pragma unroll
            for (int t = 0; t < 4; t++) sc[j][t] *= 0.125f;   // 1/sqrt(64)

        // ---- online softmax (2 rows per thread) ----
        #pragma unroll
        for (int r = 0; r < 2; r++) {
            float mx = -INFINITY;
            #pragma unroll
            for (int j = 0; j < 8; j++) {
                mx = fmaxf(mx, sc[j][2 * r]);
                mx = fmaxf(mx, sc[j][2 * r + 1]);
            }
            mx = fmaxf(mx, __shfl_xor_sync(0xFFFFFFFFu, mx, 1));
            mx = fmaxf(mx, __shfl_xor_sync(0xFFFFFFFFu, mx, 2));
            float newm = fmaxf(mrow[r], mx);
            float corr = __expf(mrow[r] - newm);
            mrow[r] = newm;
            float lsum = 0.0f;
            #pragma unroll
            for (int j = 0; j < 8; j++) {
                float e0 = __expf(sc[j][2 * r]     - newm);
                float e1 = __expf(sc[j][2 * r + 1] - newm);
                sc[j][2 * r] = e0; sc[j][2 * r + 1] = e1;
                lsum += e0 + e1;
                out[j][2 * r]     *= corr;
                out[j][2 * r + 1] *= corr;
            }
            lrow[r] = lrow[r] * corr + lsum;
        }

        // ---- P @ V (2 passes: ph.vh + pl.vh) ----
        #pragma unroll
        for (int ss = 0; ss < 4; ss++) {
            uint32_t ph[4], pl[4];
            split_pack_h(sc[2 * ss][0],     sc[2 * ss][1],     ph[0], pl[0]);
            split_pack_h(sc[2 * ss][2],     sc[2 * ss][3],     ph[1], pl[1]);
            split_pack_h(sc[2 * ss + 1][0], sc[2 * ss + 1][1], ph[2], pl[2]);
            split_pack_h(sc[2 * ss + 1][2], sc[2 * ss + 1][3], ph[3], pl[3]);

            uint32_t vh[8][2];
            #pragma unroll
            for (int j2 = 0; j2 < 4; j2++) {
                int row = ss * 16 + lm_r;
                int col = j2 * 16 + lm_c;
                uint32_t vd = smem_u32(sV + row * KSTR + col);
                ldsm_x4_t(vd, vh[2 * j2][0], vh[2 * j2][1], vh[2 * j2 + 1][0], vh[2 * j2 + 1][1]);
            }
            #pragma unroll
            for (int j = 0; j < 8; j++) mma_h(out[j], ph, vh[j]);
            #pragma unroll
            for (int j = 0; j < 8; j++) mma_h(out[j], pl, vh[j]);
        }
        __syncthreads();
        if (kt + 2 < A_NK) prefetch(kt + 2, s);
        cp_commit();
        cp_wait<1>();
        __syncthreads();
    }

    // ---- finalize ----
    #pragma unroll
    for (int r = 0; r < 2; r++) {
        lrow[r] += __shfl_xor_sync(0xFFFFFFFFu, lrow[r], 1);
        lrow[r] += __shfl_xor_sync(0xFFFFFFFFu, lrow[r], 2);
    }
    const float inv0 = 1.0f / lrow[0];
    const float inv1 = 1.0f / lrow[1];
    const int row0 = q0 + warp * 16 + g;
    #pragma unroll
    for (int j = 0; j < 8; j++) {
        int d = j * 8 + tig * 2;
        size_t addr = ((size_t)(b * SEQ + row0)) * D_MODEL + h * DHEAD + d;
        uint32_t h0, l0, h1, l1;
        split_pack_h(out[j][0] * inv0, out[j][1] * inv0, h0, l0);
        split_pack_h(out[j][2] * inv1, out[j][3] * inv1, h1, l1);
        *(uint32_t*)&Ohg[addr]               = h0;
        *(uint32_t*)&Olg[addr]               = l0;
        *(uint32_t*)&Ohg[addr + 8 * D_MODEL] = h1;
        *(uint32_t*)&Olg[addr + 8 * D_MODEL] = l1;
    }
}

// ---------------------------------------------------------------------------
// Launch
// ---------------------------------------------------------------------------
extern "C" void kernel_launch(void* const* d_in, const int* in_sizes, int n_in,
                              void* d_out, int out_size)
{
    const float* queries = (const float*)d_in[0];
    const float* keys    = (const float*)d_in[1];
    const float* values  = (const float*)d_in[2];
    const float* Wq      = (const float*)d_in[3];
    const float* bq      = (const float*)d_in[4];
    const float* Wk      = (const float*)d_in[5];
    const float* bk      = (const float*)d_in[6];
    const float* Wv      = (const float*)d_in[7];
    const float* bv      = (const float*)d_in[8];
    const float* Wo      = (const float*)d_in[9];
    const float* bo      = (const float*)d_in[10];
    float* out = (float*)d_out;

    __half *wq, *wk, *wv, *wo, *qh, *ql, *kh, *vh, *oh, *ol;
    cudaGetSymbolAddress((void**)&wq, g_wq);
    cudaGetSymbolAddress((void**)&wk, g_wk);
    cudaGetSymbolAddress((void**)&wv, g_wv);
    cudaGetSymbolAddress((void**)&wo, g_wo);
    cudaGetSymbolAddress((void**)&qh, g_qh);
    cudaGetSymbolAddress((void**)&ql, g_ql);
    cudaGetSymbolAddress((void**)&kh, g_kh);
    cudaGetSymbolAddress((void**)&vh, g_vh);
    cudaGetSymbolAddress((void**)&oh, g_oh);
    cudaGetSymbolAddress((void**)&ol, g_ol);

    cudaFuncSetAttribute(gemm_h<false, 1>, cudaFuncAttributeMaxDynamicSharedMemorySize, G_SMEM);
    cudaFuncSetAttribute(gemm_h<false, 2>, cudaFuncAttributeMaxDynamicSharedMemorySize, G_SMEM);
    cudaFuncSetAttribute(gemm_h<true, 0>,  cudaFuncAttributeMaxDynamicSharedMemorySize, G_SMEM);
    cudaFuncSetAttribute(attn_h,           cudaFuncAttributeMaxDynamicSharedMemorySize, A_SMEM);

    // 1) round weights to fp16 (one launch)
    round_w4<<<dim3((unsigned)(NW / (256 * 8)), 4), 256>>>(Wq, Wk, Wv, Wo, wq, wk, wv, wo);

    // 2) projections
    const dim3 gg(D_MODEL / 128, MROWS / 128);   // (8, 32)
    gemm_h<false, 2><<<gg, 256, G_SMEM>>>(queries, nullptr, nullptr, wq, bq,
                                          nullptr, qh, ql);
    gemm_h<false, 1><<<gg, 256, G_SMEM>>>(keys, nullptr, nullptr, wk, bk,
                                          nullptr, kh, nullptr);
    gemm_h<false, 1><<<gg, 256, G_SMEM>>>(values, nullptr, nullptr, wv, bv,
                                          nullptr, vh, nullptr);

    // 3) attention
    attn_h<<<dim3(SEQ / QBLK, NH, BATCH), 256, A_SMEM>>>(qh, ql, kh, vh, oh, ol);

    // 4) output projection (fp32 out)
    gemm_h<true, 0><<<gg, 256, G_SMEM>>>(nullptr, oh, ol, wo, bo, out, nullptr, nullptr);
}

// round 6
// speedup vs baseline: 1.4393x; 1.4135x over previous
#include <cuda_runtime.h>
#include <cuda_fp16.h>
#include <math.h>
#include <stdint.h>

#define D_MODEL 1024
#define NH      16
#define DHEAD   64
#define BATCH   4
#define SEQ     1024
#define MROWS   (BATCH * SEQ)   // 4096

// ---------------------------------------------------------------------------
// Scratch (static device globals). fp16.
// ---------------------------------------------------------------------------
#define NACT ((size_t)MROWS * D_MODEL)   // 4M
#define NW   ((size_t)D_MODEL * D_MODEL) // 1M
__device__ __half g_wq[NW], g_wk[NW], g_wv[NW], g_wo[NW];  // [K,N] fp16 rounded
__device__ __half g_qh[NACT], g_ql[NACT];   // Q split ('a' operand)
__device__ __half g_kh[NACT];               // K fp16 ('b' operand)
__device__ __half g_vh[NACT];               // V fp16 ('b' operand)
__device__ __half g_oh[NACT], g_ol[NACT];   // attn out split ('a' operand)

// ---------------------------------------------------------------------------
// Helpers
// ---------------------------------------------------------------------------
__device__ __forceinline__ uint32_t smem_u32(const void* p) {
    return (uint32_t)__cvta_generic_to_shared(p);
}
__device__ __forceinline__ void ldsm_x4(uint32_t addr, uint32_t& r0, uint32_t& r1,
                                        uint32_t& r2, uint32_t& r3) {
    asm volatile("ldmatrix.sync.aligned.m8n8.x4.shared.b16 {%0,%1,%2,%3}, [%4];"
                 : "=r"(r0), "=r"(r1), "=r"(r2), "=r"(r3) : "r"(addr));
}
__device__ __forceinline__ void ldsm_x4_t(uint32_t addr, uint32_t& r0, uint32_t& r1,
                                          uint32_t& r2, uint32_t& r3) {
    asm volatile("ldmatrix.sync.aligned.m8n8.x4.trans.shared.b16 {%0,%1,%2,%3}, [%4];"
                 : "=r"(r0), "=r"(r1), "=r"(r2), "=r"(r3) : "r"(addr));
}
__device__ __forceinline__ void mma_h(float c[4], const uint32_t a[4], const uint32_t b[2]) {
    asm volatile(
        "mma.sync.aligned.m16n8k16.row.col.f32.f16.f16.f32 "
        "{%0,%1,%2,%3}, {%4,%5,%6,%7}, {%8,%9}, {%0,%1,%2,%3};"
        : "+f"(c[0]), "+f"(c[1]), "+f"(c[2]), "+f"(c[3])
        : "r"(a[0]), "r"(a[1]), "r"(a[2]), "r"(a[3]), "r"(b[0]), "r"(b[1]));
}
__device__ __forceinline__ void split_pack_h(float x, float y, uint32_t& hi, uint32_t& lo) {
    __half xh = __float2half_rn(x);
    __half yh = __float2half_rn(y);
    __half2 h2; h2.x = xh; h2.y = yh;
    hi = *reinterpret_cast<uint32_t*>(&h2);
    float xl = x - __half2float(xh);
    float yl = y - __half2float(yh);
    __half2 l2 = __floats2half2_rn(xl, yl);
    lo = *reinterpret_cast<uint32_t*>(&l2);
}
__device__ __forceinline__ uint32_t pack_h(float x, float y) {
    __half2 h2; h2.x = __float2half_rn(x); h2.y = __float2half_rn(y);
    return *reinterpret_cast<uint32_t*>(&h2);
}

// ---------------------------------------------------------------------------
// Weight rounding: 4 weights [K,N] fp32 -> fp16, one launch.
// ---------------------------------------------------------------------------
__global__ __launch_bounds__(256)
void round_w4(const float* __restrict__ w0, const float* __restrict__ w1,
              const float* __restrict__ w2, const float* __restrict__ w3,
              __half* __restrict__ o0, __half* __restrict__ o1,
              __half* __restrict__ o2, __half* __restrict__ o3)
{
    const float* src = (blockIdx.y == 0) ? w0 : (blockIdx.y == 1) ? w1
                     : (blockIdx.y == 2) ? w2 : w3;
    __half* dst = (blockIdx.y == 0) ? o0 : (blockIdx.y == 1) ? o1
                : (blockIdx.y == 2) ? o2 : o3;
    size_t i = ((size_t)blockIdx.x * 256 + threadIdx.x) * 8;
    float4 a = *(const float4*)&src[i];
    float4 b = *(const float4*)&src[i + 4];
    uint4 o;
    o.x = pack_h(a.x, a.y); o.y = pack_h(a.z, a.w);
    o.z = pack_h(b.x, b.y); o.w = pack_h(b.z, b.w);
    *(uint4*)&dst[i] = o;
}

// ---------------------------------------------------------------------------
// Shared GEMM tiling constants (128x128x32, 8 warps, 64x32 warp tile)
// ---------------------------------------------------------------------------
#define GBK  32
#define ASTR 40
#define BSTR 136

// Core MMA loop body over one smem tile (2 passes: ah.b + al.b)
#define GEMM_TILE_MMA(sAh, sAl, sB)                                              \
    _Pragma("unroll")                                                            \
    for (int ks = 0; ks < 2; ks++) {                                             \
        uint32_t ah[4][4], al[4][4], bh[4][2];                                   \
        _Pragma("unroll")                                                        \
        for (int i = 0; i < 4; i++) {                                            \
            uint32_t ad = smem_u32(&sAh[wm + i * 16 + lm_r][ks * 16 + lm_c]);    \
            ldsm_x4(ad, ah[i][0], ah[i][1], ah[i][2], ah[i][3]);                 \
            uint32_t ad2 = smem_u32(&sAl[wm + i * 16 + lm_r][ks * 16 + lm_c]);   \
            ldsm_x4(ad2, al[i][0], al[i][1], al[i][2], al[i][3]);                \
        }                                                                        \
        _Pragma("unroll")                                                        \
        for (int j2 = 0; j2 < 2; j2++) {                                         \
            uint32_t bd = smem_u32(&sB[ks * 16 + lm_r][wn + j2 * 16 + lm_c]);    \
            ldsm_x4_t(bd, bh[2*j2][0], bh[2*j2][1], bh[2*j2+1][0], bh[2*j2+1][1]);\
        }                                                                        \
        _Pragma("unroll")                                                        \
        for (int i = 0; i < 4; i++)                                              \
            _Pragma("unroll")                                                    \
            for (int j = 0; j < 4; j++) mma_h(acc[i][j], ah[i], bh[j]);          \
        _Pragma("unroll")                                                        \
        for (int i = 0; i < 4; i++)                                              \
            _Pragma("unroll")                                                    \
            for (int j = 0; j < 4; j++) mma_h(acc[i][j], al[i], bh[j]);          \
    }

// ---------------------------------------------------------------------------
// Fused projection GEMM: z in {0,1,2} -> (queries@Wq->q split), (keys@Wk->k),
// (values@Wv->v). A fp32 (split in-kernel), W fp16.
// ---------------------------------------------------------------------------
__global__ __launch_bounds__(256, 2)
void gemm_proj(const float* __restrict__ A0, const float* __restrict__ A1,
               const float* __restrict__ A2,
               const __half* __restrict__ W0, const __half* __restrict__ W1,
               const __half* __restrict__ W2,
               const float* __restrict__ bi0, const float* __restrict__ bi1,
               const float* __restrict__ bi2,
               __half* __restrict__ Qh, __half* __restrict__ Ql,
               __half* __restrict__ Kh, __half* __restrict__ Vh)
{
    __shared__ __align__(16) __half sAh[128][ASTR];
    __shared__ __align__(16) __half sAl[128][ASTR];
    __shared__ __align__(16) __half sB[GBK][BSTR];

    const int z = blockIdx.z;
    const float*  A    = (z == 0) ? A0  : (z == 1) ? A1  : A2;
    const __half* W    = (z == 0) ? W0  : (z == 1) ? W1  : W2;
    const float*  bias = (z == 0) ? bi0 : (z == 1) ? bi1 : bi2;

    const int tid  = threadIdx.x;
    const int lane = tid & 31;
    const int warp = tid >> 5;
    const int g    = lane >> 2;
    const int tig  = lane & 3;
    const int wm   = (warp >> 2) * 64;
    const int wn   = (warp & 3) * 32;
    const int bm   = blockIdx.y * 128;
    const int bn   = blockIdx.x * 128;
    const int lm_r = (lane & 7) + ((lane >> 3) & 1) * 8;
    const int lm_c = (lane >> 4) * 8;

    float acc[4][4][4];
    #pragma unroll
    for (int i = 0; i < 4; i++)
        #pragma unroll
        for (int j = 0; j < 4; j++)
            #pragma unroll
            for (int t = 0; t < 4; t++) acc[i][j][t] = 0.0f;

    for (int k0 = 0; k0 < D_MODEL; k0 += GBK) {
        // A tile: 128x32 fp32, split -> sAh/sAl. 1024 float4, 4/thread.
        #pragma unroll
        for (int i = 0; i < 4; i++) {
            int p   = tid + i * 256;
            int row = p >> 3;
            int kk  = (p & 7) * 4;
            float4 v = *(const float4*)&A[(size_t)(bm + row) * D_MODEL + k0 + kk];
            uint32_t h0, l0, h1, l1;
            split_pack_h(v.x, v.y, h0, l0);
            split_pack_h(v.z, v.w, h1, l1);
            *(uint2*)&sAh[row][kk] = make_uint2(h0, h1);
            *(uint2*)&sAl[row][kk] = make_uint2(l0, l1);
        }
        // B tile: 32x128 fp16 copy. 512 uint4, 2/thread.
        #pragma unroll
        for (int i = 0; i < 2; i++) {
            int p   = tid + i * 256;
            int row = p >> 4;
            int c   = (p & 15) * 8;
            *(uint4*)&sB[row][c] =
                *(const uint4*)&W[(size_t)(k0 + row) * D_MODEL + bn + c];
        }
        __syncthreads();
        GEMM_TILE_MMA(sAh, sAl, sB)
        __syncthreads();
    }

    // Epilogue
    #pragma unroll
    for (int i = 0; i < 4; i++) {
        int r0 = bm + wm + i * 16 + g;
        #pragma unroll
        for (int j = 0; j < 4; j++) {
            int c = bn + wn + j * 8 + tig * 2;
            float b0 = bias[c], b1 = bias[c + 1];
            float x0 = acc[i][j][0] + b0, y0 = acc[i][j][1] + b1;
            float x1 = acc[i][j][2] + b0, y1 = acc[i][j][3] + b1;
            size_t a0 = (size_t)r0 * D_MODEL + c;
            size_t a1 = (size_t)(r0 + 8) * D_MODEL + c;
            if (z == 0) {
                uint32_t h0, l0, h1, l1;
                split_pack_h(x0, y0, h0, l0);
                split_pack_h(x1, y1, h1, l1);
                *(uint32_t*)&Qh[a0] = h0; *(uint32_t*)&Ql[a0] = l0;
                *(uint32_t*)&Qh[a1] = h1; *(uint32_t*)&Ql[a1] = l1;
            } else if (z == 1) {
                *(uint32_t*)&Kh[a0] = pack_h(x0, y0);
                *(uint32_t*)&Kh[a1] = pack_h(x1, y1);
            } else {
                *(uint32_t*)&Vh[a0] = pack_h(x0, y0);
                *(uint32_t*)&Vh[a1] = pack_h(x1, y1);
            }
        }
    }
}

// ---------------------------------------------------------------------------
// Output projection: A = presplit fp16 (oh/ol), W fp16, C fp32 + bias.
// ---------------------------------------------------------------------------
__global__ __launch_bounds__(256, 2)
void gemm_out(const __half* __restrict__ Ahg, const __half* __restrict__ Alg,
              const __half* __restrict__ W, const float* __restrict__ bias,
              float* __restrict__ C)
{
    __shared__ __align__(16) __half sAh[128][ASTR];
    __shared__ __align__(16) __half sAl[128][ASTR];
    __shared__ __align__(16) __half sB[GBK][BSTR];

    const int tid  = threadIdx.x;
    const int lane = tid & 31;
    const int warp = tid >> 5;
    const int g    = lane >> 2;
    const int tig  = lane & 3;
    const int wm   = (warp >> 2) * 64;
    const int wn   = (warp & 3) * 32;
    const int bm   = blockIdx.y * 128;
    const int bn   = blockIdx.x * 128;
    const int lm_r = (lane & 7) + ((lane >> 3) & 1) * 8;
    const int lm_c = (lane >> 4) * 8;

    float acc[4][4][4];
    #pragma unroll
    for (int i = 0; i < 4; i++)
        #pragma unroll
        for (int j = 0; j < 4; j++)
            #pragma unroll
            for (int t = 0; t < 4; t++) acc[i][j][t] = 0.0f;

    for (int k0 = 0; k0 < D_MODEL; k0 += GBK) {
        // A tiles: 128x32 fp16 x2 arrays = 1024 uint4-chunks, 4/thread.
        #pragma unroll
        for (int i = 0; i < 4; i++) {
            int p   = tid + i * 256;           // 0..1023
            int arr = p >> 9;                  // 0: hi, 1: lo
            int rem = p & 511;
            int row = rem >> 2;
            int c   = (rem & 3) * 8;
            const __half* src = arr ? Alg : Ahg;
            __half* dst = arr ? &sAl[row][c] : &sAh[row][c];
            *(uint4*)dst = *(const uint4*)&src[(size_t)(bm + row) * D_MODEL + k0 + c];
        }
        #pragma unroll
        for (int i = 0; i < 2; i++) {
            int p   = tid + i * 256;
            int row = p >> 4;
            int c   = (p & 15) * 8;
            *(uint4*)&sB[row][c] =
                *(const uint4*)&W[(size_t)(k0 + row) * D_MODEL + bn + c];
        }
        __syncthreads();
        GEMM_TILE_MMA(sAh, sAl, sB)
        __syncthreads();
    }

    #pragma unroll
    for (int i = 0; i < 4; i++) {
        int r0 = bm + wm + i * 16 + g;
        #pragma unroll
        for (int j = 0; j < 4; j++) {
            int c = bn + wn + j * 8 + tig * 2;
            float b0 = bias[c], b1 = bias[c + 1];
            *(float2*)&C[(size_t)r0 * D_MODEL + c] =
                make_float2(acc[i][j][0] + b0, acc[i][j][1] + b1);
            *(float2*)&C[(size_t)(r0 + 8) * D_MODEL + c] =
                make_float2(acc[i][j][2] + b0, acc[i][j][3] + b1);
        }
    }
}

// ---------------------------------------------------------------------------
// Flash attention, fp16 (Q hi+lo, K/V single). CTA: 128 q-rows, 8 warps.
// Static smem; Q staging region reused for K/V tiles.
// ---------------------------------------------------------------------------
#define QBLK 128
#define KBLK 64
#define KSTR 72

__global__ __launch_bounds__(256, 2)
void attn_h(const __half* __restrict__ Qhg, const __half* __restrict__ Qlg,
            const __half* __restrict__ Khg, const __half* __restrict__ Vhg,
            __half* __restrict__ Ohg, __half* __restrict__ Olg)
{
    __shared__ __align__(16) __half sm[2 * QBLK * KSTR];   // 18432 halfs = 36KB
    __half (*sK)[KSTR] = (__half(*)[KSTR])sm;              // 64 rows
    __half (*sV)[KSTR] = sK + KBLK;                        // 64 rows

    const int tid  = threadIdx.x;
    const int lane = tid & 31;
    const int warp = tid >> 5;
    const int g    = lane >> 2;
    const int tig  = lane & 3;
    const int lm_r = (lane & 7) + ((lane >> 3) & 1) * 8;
    const int lm_c = (lane >> 4) * 8;

    const int b  = blockIdx.z;
    const int h  = blockIdx.y;
    const int q0 = blockIdx.x * QBLK;
    const size_t qbase = ((size_t)(b * SEQ + q0)) * D_MODEL + h * DHEAD;

    // ---- Q staging (coalesced) then register fragments ----
    #pragma unroll
    for (int i = 0; i < 8; i++) {
        int idx = tid + i * 256;
        int arr = idx >> 10;                  // 0: hi, 1: lo
        int rem = idx & 1023;
        int row = rem >> 3;
        int c   = (rem & 7) * 8;
        const __half* src = arr ? Qlg : Qhg;
        *(uint4*)&sm[arr * 9216 + row * KSTR + c] =
            *(const uint4*)&src[qbase + (size_t)row * D_MODEL + c];
    }
    __syncthreads();
    uint32_t qh[4][4], ql[4][4];
    #pragma unroll
    for (int ks = 0; ks < 4; ks++) {
        uint32_t ad = smem_u32(&sm[(warp * 16 + lm_r) * KSTR + ks * 16 + lm_c]);
        ldsm_x4(ad, qh[ks][0], qh[ks][1], qh[ks][2], qh[ks][3]);
        uint32_t ad2 = smem_u32(&sm[9216 + (warp * 16 + lm_r) * KSTR + ks * 16 + lm_c]);
        ldsm_x4(ad2, ql[ks][0], ql[ks][1], ql[ks][2], ql[ks][3]);
    }
    __syncthreads();   // Q region now free for K/V

    float out[8][4];
    #pragma unroll
    for (int j = 0; j < 8; j++)
        #pragma unroll
        for (int t = 0; t < 4; t++) out[j][t] = 0.0f;
    float mrow[2] = {-INFINITY, -INFINITY};
    float lrow[2] = {0.0f, 0.0f};

    for (int kt = 0; kt < SEQ / KBLK; kt++) {
        const size_t gk = ((size_t)(b * SEQ + kt * KBLK)) * D_MODEL + h * DHEAD;
        // Load K,V tiles: 2 arrays x 64 rows x 8 chunks = 1024 chunks, 4/thread.
        #pragma unroll
        for (int i = 0; i < 4; i++) {
            int idx = tid + i * 256;
            int arr = idx >> 9;               // 0: K, 1: V
            int rem = idx & 511;
            int row = rem >> 3;
            int c   = (rem & 7) * 8;
            const __half* src = arr ? Vhg : Khg;
            __half* dst = arr ? &sV[row][c] : &sK[row][c];
            *(uint4*)dst = *(const uint4*)&src[gk + (size_t)row * D_MODEL + c];
        }
        __syncthreads();

        // ---- QK^T (qh.k + ql.k) ----
        float sc[8][4];
        #pragma unroll
        for (int j = 0; j < 8; j++)
            #pragma unroll
            for (int t = 0; t < 4; t++) sc[j][t] = 0.0f;

        #pragma unroll
        for (int ks = 0; ks < 4; ks++) {
            uint32_t bh[8][2];
            const int dd = ks * 16 + tig * 2;
            #pragma unroll
            for (int j = 0; j < 8; j++) {
                int key = j * 8 + g;
                bh[j][0] = *(const uint32_t*)&sK[key][dd];
                bh[j][1] = *(const uint32_t*)&sK[key][dd + 8];
            }
            #pragma unroll
            for (int j = 0; j < 8; j++) mma_h(sc[j], qh[ks], bh[j]);
            #pragma unroll
            for (int j = 0; j < 8; j++) mma_h(sc[j], ql[ks], bh[j]);
        }
        #pragma unroll
        for (int j = 0; j < 8; j++)
            #pragma unroll
            for (int t = 0; t < 4; t++) sc[j][t] *= 0.125f;

        // ---- online softmax ----
        #pragma unroll
        for (int r = 0; r < 2; r++) {
            float mx = -INFINITY;
            #pragma unroll
            for (int j = 0; j < 8; j++) {
                mx = fmaxf(mx, sc[j][2 * r]);
                mx = fmaxf(mx, sc[j][2 * r + 1]);
            }
            mx = fmaxf(mx, __shfl_xor_sync(0xFFFFFFFFu, mx, 1));
            mx = fmaxf(mx, __shfl_xor_sync(0xFFFFFFFFu, mx, 2));
            float newm = fmaxf(mrow[r], mx);
            float corr = __expf(mrow[r] - newm);
            mrow[r] = newm;
            float lsum = 0.0f;
            #pragma unroll
            for (int j = 0; j < 8; j++) {
                float e0 = __expf(sc[j][2 * r]     - newm);
                float e1 = __expf(sc[j][2 * r + 1] - newm);
                sc[j][2 * r] = e0; sc[j][2 * r + 1] = e1;
                lsum += e0 + e1;
                out[j][2 * r]     *= corr;
                out[j][2 * r + 1] *= corr;
            }
            lrow[r] = lrow[r] * corr + lsum;
        }

        // ---- P @ V (ph.v + pl.v) ----
        #pragma unroll
        for (int ss = 0; ss < 4; ss++) {
            uint32_t ph[4], pl[4];
            split_pack_h(sc[2 * ss][0],     sc[2 * ss][1],     ph[0], pl[0]);
            split_pack_h(sc[2 * ss][2],     sc[2 * ss][3],     ph[1], pl[1]);
            split_pack_h(sc[2 * ss + 1][0], sc[2 * ss + 1][1], ph[2], pl[2]);
            split_pack_h(sc[2 * ss + 1][2], sc[2 * ss + 1][3], ph[3], pl[3]);

            uint32_t vh[8][2];
            #pragma unroll
            for (int j2 = 0; j2 < 4; j2++) {
                uint32_t vd = smem_u32(&sV[ss * 16 + lm_r][j2 * 16 + lm_c]);
                ldsm_x4_t(vd, vh[2*j2][0], vh[2*j2][1], vh[2*j2+1][0], vh[2*j2+1][1]);
            }
            #pragma unroll
            for (int j = 0; j < 8; j++) mma_h(out[j], ph, vh[j]);
            #pragma unroll
            for (int j = 0; j < 8; j++) mma_h(out[j], pl, vh[j]);
        }
        __syncthreads();
    }

    // ---- finalize ----
    #pragma unroll
    for (int r = 0; r < 2; r++) {
        lrow[r] += __shfl_xor_sync(0xFFFFFFFFu, lrow[r], 1);
        lrow[r] += __shfl_xor_sync(0xFFFFFFFFu, lrow[r], 2);
    }
    const float inv0 = 1.0f / lrow[0];
    const float inv1 = 1.0f / lrow[1];
    const int row0 = q0 + warp * 16 + g;
    #pragma unroll
    for (int j = 0; j < 8; j++) {
        int d = j * 8 + tig * 2;
        size_t addr = ((size_t)(b * SEQ + row0)) * D_MODEL + h * DHEAD + d;
        uint32_t h0, l0, h1, l1;
        split_pack_h(out[j][0] * inv0, out[j][1] * inv0, h0, l0);
        split_pack_h(out[j][2] * inv1, out[j][3] * inv1, h1, l1);
        *(uint32_t*)&Ohg[addr]               = h0;
        *(uint32_t*)&Olg[addr]               = l0;
        *(uint32_t*)&Ohg[addr + 8 * D_MODEL] = h1;
        *(uint32_t*)&Olg[addr + 8 * D_MODEL] = l1;
    }
}

// ---------------------------------------------------------------------------
// Launch
// ---------------------------------------------------------------------------
extern "C" void kernel_launch(void* const* d_in, const int* in_sizes, int n_in,
                              void* d_out, int out_size)
{
    const float* queries = (const float*)d_in[0];
    const float* keys    = (const float*)d_in[1];
    const float* values  = (const float*)d_in[2];
    const float* Wq      = (const float*)d_in[3];
    const float* bq      = (const float*)d_in[4];
    const float* Wk      = (const float*)d_in[5];
    const float* bk      = (const float*)d_in[6];
    const float* Wv      = (const float*)d_in[7];
    const float* bv      = (const float*)d_in[8];
    const float* Wo      = (const float*)d_in[9];
    const float* bo      = (const float*)d_in[10];
    float* out = (float*)d_out;

    __half *wq, *wk, *wv, *wo, *qh, *ql, *kh, *vh, *oh, *ol;
    cudaGetSymbolAddress((void**)&wq, g_wq);
    cudaGetSymbolAddress((void**)&wk, g_wk);
    cudaGetSymbolAddress((void**)&wv, g_wv);
    cudaGetSymbolAddress((void**)&wo, g_wo);
    cudaGetSymbolAddress((void**)&qh, g_qh);
    cudaGetSymbolAddress((void**)&ql, g_ql);
    cudaGetSymbolAddress((void**)&kh, g_kh);
    cudaGetSymbolAddress((void**)&vh, g_vh);
    cudaGetSymbolAddress((void**)&oh, g_oh);
    cudaGetSymbolAddress((void**)&ol, g_ol);

    // 1) round weights to fp16
    round_w4<<<dim3((unsigned)(NW / (256 * 8)), 4), 256>>>(Wq, Wk, Wv, Wo, wq, wk, wv, wo);

    // 2) fused Q/K/V projections
    gemm_proj<<<dim3(D_MODEL / 128, MROWS / 128, 3), 256>>>(
        queries, keys, values, wq, wk, wv, bq, bk, bv, qh, ql, kh, vh);

    // 3) attention
    attn_h<<<dim3(SEQ / QBLK, NH, BATCH), 256>>>(qh, ql, kh, vh, oh, ol);

    // 4) output projection (fp32 out)
    gemm_out<<<dim3(D_MODEL / 128, MROWS / 128), 256>>>(oh, ol, wo, bo, out);
}

// round 7
// speedup vs baseline: 1.4535x; 1.0099x over previous
#include <cuda_runtime.h>
#include <cuda_fp16.h>
#include <math.h>
#include <stdint.h>

#define D_MODEL 1024
#define NH      16
#define DHEAD   64
#define BATCH   4
#define SEQ     1024
#define MROWS   (BATCH * SEQ)   // 4096

// ---------------------------------------------------------------------------
// Scratch (static device globals). fp16.
// ---------------------------------------------------------------------------
#define NACT ((size_t)MROWS * D_MODEL)   // 4M
#define NW   ((size_t)D_MODEL * D_MODEL) // 1M
__device__ __half g_wq[NW], g_wk[NW], g_wv[NW], g_wo[NW];   // [K,N] fp16
__device__ __half g_xh[3][NACT], g_xl[3][NACT];             // split activations
__device__ __half g_qh[NACT], g_ql[NACT];                   // Q split
__device__ __half g_kh[NACT];                               // K fp16
__device__ __half g_vh[NACT];                               // V fp16
__device__ __half g_oh[NACT], g_ol[NACT];                   // attn out split

// ---------------------------------------------------------------------------
// Helpers
// ---------------------------------------------------------------------------
__device__ __forceinline__ uint32_t smem_u32(const void* p) {
    return (uint32_t)__cvta_generic_to_shared(p);
}
__device__ __forceinline__ void cp_async16(uint32_t dst, const void* src) {
    asm volatile("cp.async.cg.shared.global [%0], [%1], 16;" :: "r"(dst), "l"(src));
}
__device__ __forceinline__ void cp_commit() {
    asm volatile("cp.async.commit_group;");
}
template <int N>
__device__ __forceinline__ void cp_wait() {
    asm volatile("cp.async.wait_group %0;" :: "n"(N));
}
__device__ __forceinline__ void ldsm_x4(uint32_t addr, uint32_t& r0, uint32_t& r1,
                                        uint32_t& r2, uint32_t& r3) {
    asm volatile("ldmatrix.sync.aligned.m8n8.x4.shared.b16 {%0,%1,%2,%3}, [%4];"
                 : "=r"(r0), "=r"(r1), "=r"(r2), "=r"(r3) : "r"(addr));
}
__device__ __forceinline__ void ldsm_x4_t(uint32_t addr, uint32_t& r0, uint32_t& r1,
                                          uint32_t& r2, uint32_t& r3) {
    asm volatile("ldmatrix.sync.aligned.m8n8.x4.trans.shared.b16 {%0,%1,%2,%3}, [%4];"
                 : "=r"(r0), "=r"(r1), "=r"(r2), "=r"(r3) : "r"(addr));
}
__device__ __forceinline__ void mma_h(float c[4], const uint32_t a[4], const uint32_t b[2]) {
    asm volatile(
        "mma.sync.aligned.m16n8k16.row.col.f32.f16.f16.f32 "
        "{%0,%1,%2,%3}, {%4,%5,%6,%7}, {%8,%9}, {%0,%1,%2,%3};"
        : "+f"(c[0]), "+f"(c[1]), "+f"(c[2]), "+f"(c[3])
        : "r"(a[0]), "r"(a[1]), "r"(a[2]), "r"(a[3]), "r"(b[0]), "r"(b[1]));
}
__device__ __forceinline__ void split_pack_h(float x, float y, uint32_t& hi, uint32_t& lo) {
    __half xh = __float2half_rn(x);
    __half yh = __float2half_rn(y);
    __half2 h2; h2.x = xh; h2.y = yh;
    hi = *reinterpret_cast<uint32_t*>(&h2);
    float xl = x - __half2float(xh);
    float yl = y - __half2float(yh);
    __half2 l2 = __floats2half2_rn(xl, yl);
    lo = *reinterpret_cast<uint32_t*>(&l2);
}
__device__ __forceinline__ uint32_t pack_h(float x, float y) {
    __half2 h2; h2.x = __float2half_rn(x); h2.y = __float2half_rn(y);
    return *reinterpret_cast<uint32_t*>(&h2);
}

// ---------------------------------------------------------------------------
// Preprocessing: round 4 weights; split 3 activations. One launch each.
// ---------------------------------------------------------------------------
__global__ __launch_bounds__(256)
void round_w4(const float* __restrict__ w0, const float* __restrict__ w1,
              const float* __restrict__ w2, const float* __restrict__ w3,
              __half* __restrict__ o0, __half* __restrict__ o1,
              __half* __restrict__ o2, __half* __restrict__ o3)
{
    const float* src = (blockIdx.y == 0) ? w0 : (blockIdx.y == 1) ? w1
                     : (blockIdx.y == 2) ? w2 : w3;
    __half* dst = (blockIdx.y == 0) ? o0 : (blockIdx.y == 1) ? o1
                : (blockIdx.y == 2) ? o2 : o3;
    size_t i = ((size_t)blockIdx.x * 256 + threadIdx.x) * 8;
    float4 a = *(const float4*)&src[i];
    float4 b = *(const float4*)&src[i + 4];
    uint4 o;
    o.x = pack_h(a.x, a.y); o.y = pack_h(a.z, a.w);
    o.z = pack_h(b.x, b.y); o.w = pack_h(b.z, b.w);
    *(uint4*)&dst[i] = o;
}

__global__ __launch_bounds__(256)
void split_act3(const float* __restrict__ a0, const float* __restrict__ a1,
                const float* __restrict__ a2,
                __half* __restrict__ h0, __half* __restrict__ l0_,
                __half* __restrict__ h1, __half* __restrict__ l1_,
                __half* __restrict__ h2, __half* __restrict__ l2_)
{
    const float* src = (blockIdx.y == 0) ? a0 : (blockIdx.y == 1) ? a1 : a2;
    __half* dh = (blockIdx.y == 0) ? h0 : (blockIdx.y == 1) ? h1 : h2;
    __half* dl = (blockIdx.y == 0) ? l0_ : (blockIdx.y == 1) ? l1_ : l2_;
    size_t i = ((size_t)blockIdx.x * 256 + threadIdx.x) * 4;
    float4 v = *(const float4*)&src[i];
    uint32_t ha, la, hb, lb;
    split_pack_h(v.x, v.y, ha, la);
    split_pack_h(v.z, v.w, hb, lb);
    *(uint2*)&dh[i] = make_uint2(ha, hb);
    *(uint2*)&dl[i] = make_uint2(la, lb);
}

// ---------------------------------------------------------------------------
// Unified GEMM: C = A @ W + bias. A presplit fp16 (hi/lo), W fp16 [K,N].
// 128x128x32 tiles, 8 warps (64x32 warp tile), 2-stage cp.async pipeline.
// PROJ: fused z in {0,1,2} -> Q(split out) / K(fp16) / V(fp16).
// else: fp32 out (output projection).
// ---------------------------------------------------------------------------
#define GBK  32
#define ASTR 40
#define BSTR 136
#define G_A  (128 * ASTR)            // 5120 halfs per A array
#define G_B  (GBK * BSTR)            // 4352 halfs
#define G_ST (2 * G_A + G_B)         // 14592 halfs per stage
#define G_SMEMB (2 * G_ST * 2)       // 58368 B
#define G_NK (D_MODEL / GBK)         // 32

template <bool PROJ>
__global__ __launch_bounds__(256, 2)
void gemm_u(const __half* __restrict__ Ah0, const __half* __restrict__ Al0,
            const __half* __restrict__ Ah1, const __half* __restrict__ Al1,
            const __half* __restrict__ Ah2, const __half* __restrict__ Al2,
            const __half* __restrict__ W0, const __half* __restrict__ W1,
            const __half* __restrict__ W2,
            const float* __restrict__ bi0, const float* __restrict__ bi1,
            const float* __restrict__ bi2,
            __half* __restrict__ Qh, __half* __restrict__ Ql,
            __half* __restrict__ Kh, __half* __restrict__ Vh,
            float* __restrict__ Cf)
{
    extern __shared__ __align__(16) __half dsm[];

    const int z = PROJ ? blockIdx.z : 0;
    const __half* Ahg  = (z == 0) ? Ah0 : (z == 1) ? Ah1 : Ah2;
    const __half* Alg  = (z == 0) ? Al0 : (z == 1) ? Al1 : Al2;
    const __half* W    = (z == 0) ? W0  : (z == 1) ? W1  : W2;
    const float*  bias = (z == 0) ? bi0 : (z == 1) ? bi1 : bi2;

    const int tid  = threadIdx.x;
    const int lane = tid & 31;
    const int warp = tid >> 5;
    const int g    = lane >> 2;
    const int tig  = lane & 3;
    const int wm   = (warp >> 2) * 64;
    const int wn   = (warp & 3) * 32;
    const int bm   = blockIdx.y * 128;
    const int bn   = blockIdx.x * 128;
    const int lm_r = (lane & 7) + ((lane >> 3) & 1) * 8;
    const int lm_c = (lane >> 4) * 8;

    float acc[4][4][4];
    #pragma unroll
    for (int i = 0; i < 4; i++)
        #pragma unroll
        for (int j = 0; j < 4; j++)
            #pragma unroll
            for (int t = 0; t < 4; t++) acc[i][j][t] = 0.0f;

    // cp.async loader: A (2 arrays x 128 rows x 4 chunks) + B (32 rows x 16 chunks)
    auto load_tile = [&](int kt, int s) {
        __half* base = dsm + s * G_ST;
        const int k0 = kt * GBK;
        #pragma unroll
        for (int i = 0; i < 4; i++) {
            int p   = tid + i * 256;          // 0..1023
            int arr = p >> 9;                 // 0: hi, 1: lo
            int rem = p & 511;
            int row = rem >> 2;               // 0..127
            int c   = (rem & 3) * 8;          // 0..24
            const __half* src = arr ? Alg : Ahg;
            cp_async16(smem_u32(base + arr * G_A + row * ASTR + c),
                       src + (size_t)(bm + row) * D_MODEL + k0 + c);
        }
        #pragma unroll
        for (int i = 0; i < 2; i++) {
            int p   = tid + i * 256;          // 0..511
            int row = p >> 4;                 // 0..31
            int c   = (p & 15) * 8;           // 0..120
            cp_async16(smem_u32(base + 2 * G_A + row * BSTR + c),
                       W + (size_t)(k0 + row) * D_MODEL + bn + c);
        }
    };

    load_tile(0, 0); cp_commit();
    load_tile(1, 1); cp_commit();

    for (int kt = 0; kt < G_NK; kt++) {
        const int s = kt & 1;
        if (kt == G_NK - 1) cp_wait<0>(); else cp_wait<1>();
        __syncthreads();
        __half* sAh = dsm + s * G_ST;
        __half* sAl = sAh + G_A;
        __half* sB  = sAh + 2 * G_A;

        #pragma unroll
        for (int ks = 0; ks < 2; ks++) {
            uint32_t ah[4][4], al[4][4], bh[4][2];
            #pragma unroll
            for (int i = 0; i < 4; i++) {
                uint32_t ad = smem_u32(sAh + (wm + i * 16 + lm_r) * ASTR + ks * 16 + lm_c);
                ldsm_x4(ad, ah[i][0], ah[i][1], ah[i][2], ah[i][3]);
                uint32_t ad2 = smem_u32(sAl + (wm + i * 16 + lm_r) * ASTR + ks * 16 + lm_c);
                ldsm_x4(ad2, al[i][0], al[i][1], al[i][2], al[i][3]);
            }
            #pragma unroll
            for (int j2 = 0; j2 < 2; j2++) {
                uint32_t bd = smem_u32(sB + (ks * 16 + lm_r) * BSTR + wn + j2 * 16 + lm_c);
                ldsm_x4_t(bd, bh[2*j2][0], bh[2*j2][1], bh[2*j2+1][0], bh[2*j2+1][1]);
            }
            #pragma unroll
            for (int i = 0; i < 4; i++)
                #pragma unroll
                for (int j = 0; j < 4; j++) mma_h(acc[i][j], ah[i], bh[j]);
            #pragma unroll
            for (int i = 0; i < 4; i++)
                #pragma unroll
                for (int j = 0; j < 4; j++) mma_h(acc[i][j], al[i], bh[j]);
        }
        __syncthreads();
        if (kt + 2 < G_NK) load_tile(kt + 2, s);
        cp_commit();
    }

    // Epilogue
    #pragma unroll
    for (int i = 0; i < 4; i++) {
        int r0 = bm + wm + i * 16 + g;
        #pragma unroll
        for (int j = 0; j < 4; j++) {
            int c = bn + wn + j * 8 + tig * 2;
            float b0 = bias[c], b1 = bias[c + 1];
            float x0 = acc[i][j][0] + b0, y0 = acc[i][j][1] + b1;
            float x1 = acc[i][j][2] + b0, y1 = acc[i][j][3] + b1;
            size_t a0 = (size_t)r0 * D_MODEL + c;
            size_t a1 = (size_t)(r0 + 8) * D_MODEL + c;
            if (!PROJ) {
                *(float2*)&Cf[a0] = make_float2(x0, y0);
                *(float2*)&Cf[a1] = make_float2(x1, y1);
            } else if (z == 0) {
                uint32_t h0, l0, h1, l1;
                split_pack_h(x0, y0, h0, l0);
                split_pack_h(x1, y1, h1, l1);
                *(uint32_t*)&Qh[a0] = h0; *(uint32_t*)&Ql[a0] = l0;
                *(uint32_t*)&Qh[a1] = h1; *(uint32_t*)&Ql[a1] = l1;
            } else if (z == 1) {
                *(uint32_t*)&Kh[a0] = pack_h(x0, y0);
                *(uint32_t*)&Kh[a1] = pack_h(x1, y1);
            } else {
                *(uint32_t*)&Vh[a0] = pack_h(x0, y0);
                *(uint32_t*)&Vh[a1] = pack_h(x1, y1);
            }
        }
    }
}

// ---------------------------------------------------------------------------
// Flash attention, fp16 (Q hi+lo, K/V single), 2-stage cp.async K/V pipeline.
// CTA: 128 q-rows of one (b,h), 8 warps.
// ---------------------------------------------------------------------------
#define QBLK 128
#define KBLK 64
#define KSTR 72
#define KV_ARR (KBLK * KSTR)          // 4608 halfs
#define KV_ST  (2 * KV_ARR)           // 9216 halfs per stage (K+V)
#define A_SMEMB (2 * KV_ST * 2)       // 36864 B
#define A_NK (SEQ / KBLK)             // 16

__global__ __launch_bounds__(256, 2)
void attn_h(const __half* __restrict__ Qhg, const __half* __restrict__ Qlg,
            const __half* __restrict__ Khg, const __half* __restrict__ Vhg,
            __half* __restrict__ Ohg, __half* __restrict__ Olg)
{
    extern __shared__ __align__(16) __half dsm[];

    const int tid  = threadIdx.x;
    const int lane = tid & 31;
    const int warp = tid >> 5;
    const int g    = lane >> 2;
    const int tig  = lane & 3;
    const int lm_r = (lane & 7) + ((lane >> 3) & 1) * 8;
    const int lm_c = (lane >> 4) * 8;

    const int b  = blockIdx.z;
    const int h  = blockIdx.y;
    const int q0 = blockIdx.x * QBLK;
    const size_t qbase = ((size_t)(b * SEQ + q0)) * D_MODEL + h * DHEAD;

    // ---- Q staging across both stages, then register fragments ----
    #pragma unroll
    for (int i = 0; i < 8; i++) {
        int idx = tid + i * 256;
        int arr = idx >> 10;                  // 0: hi, 1: lo
        int rem = idx & 1023;
        int row = rem >> 3;
        int c   = (rem & 7) * 8;
        const __half* src = arr ? Qlg : Qhg;
        *(uint4*)&dsm[arr * 9216 + row * KSTR + c] =
            *(const uint4*)&src[qbase + (size_t)row * D_MODEL + c];
    }
    __syncthreads();
    uint32_t qh[4][4], ql[4][4];
    #pragma unroll
    for (int ks = 0; ks < 4; ks++) {
        uint32_t ad = smem_u32(&dsm[(warp * 16 + lm_r) * KSTR + ks * 16 + lm_c]);
        ldsm_x4(ad, qh[ks][0], qh[ks][1], qh[ks][2], qh[ks][3]);
        uint32_t ad2 = smem_u32(&dsm[9216 + (warp * 16 + lm_r) * KSTR + ks * 16 + lm_c]);
        ldsm_x4(ad2, ql[ks][0], ql[ks][1], ql[ks][2], ql[ks][3]);
    }
    __syncthreads();   // smem now free for K/V pipeline

    auto prefetch = [&](int kt, int s) {
        __half* base = dsm + s * KV_ST;
        const size_t gk = ((size_t)(b * SEQ + kt * KBLK)) * D_MODEL + h * DHEAD;
        #pragma unroll
        for (int i = 0; i < 4; i++) {
            int idx = tid + i * 256;
            int arr = idx >> 9;               // 0: K, 1: V
            int rem = idx & 511;
            int row = rem >> 3;
            int c   = (rem & 7) * 8;
            const __half* src = arr ? Vhg : Khg;
            cp_async16(smem_u32(base + arr * KV_ARR + row * KSTR + c),
                       src + gk + (size_t)row * D_MODEL + c);
        }
    };

    float out[8][4];
    #pragma unroll
    for (int j = 0; j < 8; j++)
        #pragma unroll
        for (int t = 0; t < 4; t++) out[j][t] = 0.0f;
    float mrow[2] = {-INFINITY, -INFINITY};
    float lrow[2] = {0.0f, 0.0f};

    prefetch(0, 0); cp_commit();
    prefetch(1, 1); cp_commit();

    for (int kt = 0; kt < A_NK; kt++) {
        const int s = kt & 1;
        if (kt == A_NK - 1) cp_wait<0>(); else cp_wait<1>();
        __syncthreads();
        __half* sK = dsm + s * KV_ST;
        __half* sV = sK + KV_ARR;

        // ---- QK^T (qh.k + ql.k) ----
        float sc[8][4];
        #pragma unroll
        for (int j = 0; j < 8; j++)
            #pragma unroll
            for (int t = 0; t < 4; t++) sc[j][t] = 0.0f;

        #pragma unroll
        for (int ks = 0; ks < 4; ks++) {
            uint32_t bh[8][2];
            const int dd = ks * 16 + tig * 2;
            #pragma unroll
            for (int j = 0; j < 8; j++) {
                int key = j * 8 + g;
                bh[j][0] = *(const uint32_t*)(sK + key * KSTR + dd);
                bh[j][1] = *(const uint32_t*)(sK + key * KSTR + dd + 8);
            }
            #pragma unroll
            for (int j = 0; j < 8; j++) mma_h(sc[j], qh[ks], bh[j]);
            #pragma unroll
            for (int j = 0; j < 8; j++) mma_h(sc[j], ql[ks], bh[j]);
        }
        #pragma unroll
        for (int j = 0; j < 8; j++)
            #pragma unroll
            for (int t = 0; t < 4; t++) sc[j][t] *= 0.125f;

        // ---- online softmax ----
        #pragma unroll
        for (int r = 0; r < 2; r++) {
            float mx = -INFINITY;
            #pragma unroll
            for (int j = 0; j < 8; j++) {
                mx = fmaxf(mx, sc[j][2 * r]);
                mx = fmaxf(mx, sc[j][2 * r + 1]);
            }
            mx = fmaxf(mx, __shfl_xor_sync(0xFFFFFFFFu, mx, 1));
            mx = fmaxf(mx, __shfl_xor_sync(0xFFFFFFFFu, mx, 2));
            float newm = fmaxf(mrow[r], mx);
            float corr = __expf(mrow[r] - newm);
            mrow[r] = newm;
            float lsum = 0.0f;
            #pragma unroll
            for (int j = 0; j < 8; j++) {
                float e0 = __expf(sc[j][2 * r]     - newm);
                float e1 = __expf(sc[j][2 * r + 1] - newm);
                sc[j][2 * r] = e0; sc[j][2 * r + 1] = e1;
                lsum += e0 + e1;
                out[j][2 * r]     *= corr;
                out[j][2 * r + 1] *= corr;
            }
            lrow[r] = lrow[r] * corr + lsum;
        }

        // ---- P @ V (ph.v + pl.v) ----
        #pragma unroll
        for (int ss = 0; ss < 4; ss++) {
            uint32_t ph[4], pl[4];
            split_pack_h(sc[2 * ss][0],     sc[2 * ss][1],     ph[0], pl[0]);
            split_pack_h(sc[2 * ss][2],     sc[2 * ss][3],     ph[1], pl[1]);
            split_pack_h(sc[2 * ss + 1][0], sc[2 * ss + 1][1], ph[2], pl[2]);
            split_pack_h(sc[2 * ss + 1][2], sc[2 * ss + 1][3], ph[3], pl[3]);

            uint32_t vh[8][2];
            #pragma unroll
            for (int j2 = 0; j2 < 4; j2++) {
                uint32_t vd = smem_u32(sV + (ss * 16 + lm_r) * KSTR + j2 * 16 + lm_c);
                ldsm_x4_t(vd, vh[2*j2][0], vh[2*j2][1], vh[2*j2+1][0], vh[2*j2+1][1]);
            }
            #pragma unroll
            for (int j = 0; j < 8; j++) mma_h(out[j], ph, vh[j]);
            #pragma unroll
            for (int j = 0; j < 8; j++) mma_h(out[j], pl, vh[j]);
        }
        __syncthreads();
        if (kt + 2 < A_NK) prefetch(kt + 2, s);
        cp_commit();
    }

    // ---- finalize ----
    #pragma unroll
    for (int r = 0; r < 2; r++) {
        lrow[r] += __shfl_xor_sync(0xFFFFFFFFu, lrow[r], 1);
        lrow[r] += __shfl_xor_sync(0xFFFFFFFFu, lrow[r], 2);
    }
    const float inv0 = 1.0f / lrow[0];
    const float inv1 = 1.0f / lrow[1];
    const int row0 = q0 + warp * 16 + g;
    #pragma unroll
    for (int j = 0; j < 8; j++) {
        int d = j * 8 + tig * 2;
        size_t addr = ((size_t)(b * SEQ + row0)) * D_MODEL + h * DHEAD + d;
        uint32_t h0, l0, h1, l1;
        split_pack_h(out[j][0] * inv0, out[j][1] * inv0, h0, l0);
        split_pack_h(out[j][2] * inv1, out[j][3] * inv1, h1, l1);
        *(uint32_t*)&Ohg[addr]               = h0;
        *(uint32_t*)&Olg[addr]               = l0;
        *(uint32_t*)&Ohg[addr + 8 * D_MODEL] = h1;
        *(uint32_t*)&Olg[addr + 8 * D_MODEL] = l1;
    }
}

// ---------------------------------------------------------------------------
// Launch
// ---------------------------------------------------------------------------
extern "C" void kernel_launch(void* const* d_in, const int* in_sizes, int n_in,
                              void* d_out, int out_size)
{
    const float* queries = (const float*)d_in[0];
    const float* keys    = (const float*)d_in[1];
    const float* values  = (const float*)d_in[2];
    const float* Wq      = (const float*)d_in[3];
    const float* bq      = (const float*)d_in[4];
    const float* Wk      = (const float*)d_in[5];
    const float* bk      = (const float*)d_in[6];
    const float* Wv      = (const float*)d_in[7];
    const float* bv      = (const float*)d_in[8];
    const float* Wo      = (const float*)d_in[9];
    const float* bo      = (const float*)d_in[10];
    float* out = (float*)d_out;

    __half *wq, *wk, *wv, *wo, *qh, *ql, *kh, *vh, *oh, *ol;
    __half *xh0, *xl0, *xh1, *xl1, *xh2, *xl2;
    cudaGetSymbolAddress((void**)&wq, g_wq);
    cudaGetSymbolAddress((void**)&wk, g_wk);
    cudaGetSymbolAddress((void**)&wv, g_wv);
    cudaGetSymbolAddress((void**)&wo, g_wo);
    cudaGetSymbolAddress((void**)&qh, g_qh);
    cudaGetSymbolAddress((void**)&ql, g_ql);
    cudaGetSymbolAddress((void**)&kh, g_kh);
    cudaGetSymbolAddress((void**)&vh, g_vh);
    cudaGetSymbolAddress((void**)&oh, g_oh);
    cudaGetSymbolAddress((void**)&ol, g_ol);
    {
        __half* base;
        cudaGetSymbolAddress((void**)&base, g_xh);
        xh0 = base; xh1 = base + NACT; xh2 = base + 2 * NACT;
        cudaGetSymbolAddress((void**)&base, g_xl);
        xl0 = base; xl1 = base + NACT; xl2 = base + 2 * NACT;
    }

    cudaFuncSetAttribute(gemm_u<true>,  cudaFuncAttributeMaxDynamicSharedMemorySize, G_SMEMB);
    cudaFuncSetAttribute(gemm_u<false>, cudaFuncAttributeMaxDynamicSharedMemorySize, G_SMEMB);
    cudaFuncSetAttribute(attn_h,        cudaFuncAttributeMaxDynamicSharedMemorySize, A_SMEMB);

    // 1) preprocessing: round weights, split activations
    round_w4<<<dim3((unsigned)(NW / (256 * 8)), 4), 256>>>(Wq, Wk, Wv, Wo, wq, wk, wv, wo);
    split_act3<<<dim3((unsigned)(NACT / (256 * 4)), 3), 256>>>(
        queries, keys, values, xh0, xl0, xh1, xl1, xh2, xl2);

    // 2) fused Q/K/V projections (cp.async pipeline)
    gemm_u<true><<<dim3(D_MODEL / 128, MROWS / 128, 3), 256, G_SMEMB>>>(
        xh0, xl0, xh1, xl1, xh2, xl2, wq, wk, wv, bq, bk, bv,
        qh, ql, kh, vh, nullptr);

    // 3) attention
    attn_h<<<dim3(SEQ / QBLK, NH, BATCH), 256, A_SMEMB>>>(qh, ql, kh, vh, oh, ol);

    // 4) output projection (fp32 out)
    gemm_u<false><<<dim3(D_MODEL / 128, MROWS / 128, 1), 256, G_SMEMB>>>(
        oh, ol, nullptr, nullptr, nullptr, nullptr, wo, nullptr, nullptr,
        bo, nullptr, nullptr, nullptr, nullptr, nullptr, nullptr, out);
}

// round 8
// speedup vs baseline: 1.5855x; 1.0908x over previous
#include <cuda_runtime.h>
#include <cuda_fp16.h>
#include <math.h>
#include <stdint.h>

#define D_MODEL 1024
#define NH      16
#define DHEAD   64
#define BATCH   4
#define SEQ     1024
#define MROWS   (BATCH * SEQ)   // 4096

// ---------------------------------------------------------------------------
// Scratch (static device globals). fp16.
// ---------------------------------------------------------------------------
#define NACT ((size_t)MROWS * D_MODEL)   // 4M
#define NW   ((size_t)D_MODEL * D_MODEL) // 1M
__device__ __half g_wq[NW], g_wk[NW], g_wv[NW], g_wo[NW];   // [K,N] fp16
__device__ __half g_xh[3][NACT], g_xl[3][NACT];             // split activations
__device__ __half g_qh[NACT], g_ql[NACT];                   // Q split
__device__ __half g_kh[NACT];                               // K fp16
__device__ __half g_vh[NACT];                               // V fp16
__device__ __half g_oh[NACT], g_ol[NACT];                   // attn out split

// ---------------------------------------------------------------------------
// Helpers
// ---------------------------------------------------------------------------
__device__ __forceinline__ uint32_t smem_u32(const void* p) {
    return (uint32_t)__cvta_generic_to_shared(p);
}
__device__ __forceinline__ void cp_async16(uint32_t dst, const void* src) {
    asm volatile("cp.async.cg.shared.global [%0], [%1], 16;" :: "r"(dst), "l"(src));
}
__device__ __forceinline__ void cp_commit() {
    asm volatile("cp.async.commit_group;");
}
template <int N>
__device__ __forceinline__ void cp_wait() {
    asm volatile("cp.async.wait_group %0;" :: "n"(N));
}
__device__ __forceinline__ void ldsm_x4(uint32_t addr, uint32_t& r0, uint32_t& r1,
                                        uint32_t& r2, uint32_t& r3) {
    asm volatile("ldmatrix.sync.aligned.m8n8.x4.shared.b16 {%0,%1,%2,%3}, [%4];"
                 : "=r"(r0), "=r"(r1), "=r"(r2), "=r"(r3) : "r"(addr));
}
__device__ __forceinline__ void ldsm_x4_t(uint32_t addr, uint32_t& r0, uint32_t& r1,
                                          uint32_t& r2, uint32_t& r3) {
    asm volatile("ldmatrix.sync.aligned.m8n8.x4.trans.shared.b16 {%0,%1,%2,%3}, [%4];"
                 : "=r"(r0), "=r"(r1), "=r"(r2), "=r"(r3) : "r"(addr));
}
__device__ __forceinline__ void mma_h(float c[4], const uint32_t a[4], const uint32_t b[2]) {
    asm volatile(
        "mma.sync.aligned.m16n8k16.row.col.f32.f16.f16.f32 "
        "{%0,%1,%2,%3}, {%4,%5,%6,%7}, {%8,%9}, {%0,%1,%2,%3};"
        : "+f"(c[0]), "+f"(c[1]), "+f"(c[2]), "+f"(c[3])
        : "r"(a[0]), "r"(a[1]), "r"(a[2]), "r"(a[3]), "r"(b[0]), "r"(b[1]));
}
__device__ __forceinline__ void split_pack_h(float x, float y, uint32_t& hi, uint32_t& lo) {
    __half xh = __float2half_rn(x);
    __half yh = __float2half_rn(y);
    __half2 h2; h2.x = xh; h2.y = yh;
    hi = *reinterpret_cast<uint32_t*>(&h2);
    float xl = x - __half2float(xh);
    float yl = y - __half2float(yh);
    __half2 l2 = __floats2half2_rn(xl, yl);
    lo = *reinterpret_cast<uint32_t*>(&l2);
}
__device__ __forceinline__ uint32_t pack_h(float x, float y) {
    __half2 h2; h2.x = __float2half_rn(x); h2.y = __float2half_rn(y);
    return *reinterpret_cast<uint32_t*>(&h2);
}

// ---------------------------------------------------------------------------
// Preprocessing: round 4 weights; split 3 activations.
// ---------------------------------------------------------------------------
__global__ __launch_bounds__(256)
void round_w4(const float* __restrict__ w0, const float* __restrict__ w1,
              const float* __restrict__ w2, const float* __restrict__ w3,
              __half* __restrict__ o0, __half* __restrict__ o1,
              __half* __restrict__ o2, __half* __restrict__ o3)
{
    const float* src = (blockIdx.y == 0) ? w0 : (blockIdx.y == 1) ? w1
                     : (blockIdx.y == 2) ? w2 : w3;
    __half* dst = (blockIdx.y == 0) ? o0 : (blockIdx.y == 1) ? o1
                : (blockIdx.y == 2) ? o2 : o3;
    size_t i = ((size_t)blockIdx.x * 256 + threadIdx.x) * 8;
    float4 a = *(const float4*)&src[i];
    float4 b = *(const float4*)&src[i + 4];
    uint4 o;
    o.x = pack_h(a.x, a.y); o.y = pack_h(a.z, a.w);
    o.z = pack_h(b.x, b.y); o.w = pack_h(b.z, b.w);
    *(uint4*)&dst[i] = o;
}

__global__ __launch_bounds__(256)
void split_act3(const float* __restrict__ a0, const float* __restrict__ a1,
                const float* __restrict__ a2,
                __half* __restrict__ h0, __half* __restrict__ l0_,
                __half* __restrict__ h1, __half* __restrict__ l1_,
                __half* __restrict__ h2, __half* __restrict__ l2_)
{
    const float* src = (blockIdx.y == 0) ? a0 : (blockIdx.y == 1) ? a1 : a2;
    __half* dh = (blockIdx.y == 0) ? h0 : (blockIdx.y == 1) ? h1 : h2;
    __half* dl = (blockIdx.y == 0) ? l0_ : (blockIdx.y == 1) ? l1_ : l2_;
    size_t i = ((size_t)blockIdx.x * 256 + threadIdx.x) * 4;
    float4 v = *(const float4*)&src[i];
    uint32_t ha, la, hb, lb;
    split_pack_h(v.x, v.y, ha, la);
    split_pack_h(v.z, v.w, hb, lb);
    *(uint2*)&dh[i] = make_uint2(ha, hb);
    *(uint2*)&dl[i] = make_uint2(la, lb);
}

// ---------------------------------------------------------------------------
// Unified GEMM (unchanged from R7): C = A @ W + bias, 2-stage cp.async.
// ---------------------------------------------------------------------------
#define GBK  32
#define ASTR 40
#define BSTR 136
#define G_A  (128 * ASTR)
#define G_B  (GBK * BSTR)
#define G_ST (2 * G_A + G_B)
#define G_SMEMB (2 * G_ST * 2)
#define G_NK (D_MODEL / GBK)

template <bool PROJ>
__global__ __launch_bounds__(256, 2)
void gemm_u(const __half* __restrict__ Ah0, const __half* __restrict__ Al0,
            const __half* __restrict__ Ah1, const __half* __restrict__ Al1,
            const __half* __restrict__ Ah2, const __half* __restrict__ Al2,
            const __half* __restrict__ W0, const __half* __restrict__ W1,
            const __half* __restrict__ W2,
            const float* __restrict__ bi0, const float* __restrict__ bi1,
            const float* __restrict__ bi2,
            __half* __restrict__ Qh, __half* __restrict__ Ql,
            __half* __restrict__ Kh, __half* __restrict__ Vh,
            float* __restrict__ Cf)
{
    extern __shared__ __align__(16) __half dsm[];

    const int z = PROJ ? blockIdx.z : 0;
    const __half* Ahg  = (z == 0) ? Ah0 : (z == 1) ? Ah1 : Ah2;
    const __half* Alg  = (z == 0) ? Al0 : (z == 1) ? Al1 : Al2;
    const __half* W    = (z == 0) ? W0  : (z == 1) ? W1  : W2;
    const float*  bias = (z == 0) ? bi0 : (z == 1) ? bi1 : bi2;

    const int tid  = threadIdx.x;
    const int lane = tid & 31;
    const int warp = tid >> 5;
    const int g    = lane >> 2;
    const int tig  = lane & 3;
    const int wm   = (warp >> 2) * 64;
    const int wn   = (warp & 3) * 32;
    const int bm   = blockIdx.y * 128;
    const int bn   = blockIdx.x * 128;
    const int lm_r = (lane & 7) + ((lane >> 3) & 1) * 8;
    const int lm_c = (lane >> 4) * 8;

    float acc[4][4][4];
    #pragma unroll
    for (int i = 0; i < 4; i++)
        #pragma unroll
        for (int j = 0; j < 4; j++)
            #pragma unroll
            for (int t = 0; t < 4; t++) acc[i][j][t] = 0.0f;

    auto load_tile = [&](int kt, int s) {
        __half* base = dsm + s * G_ST;
        const int k0 = kt * GBK;
        #pragma unroll
        for (int i = 0; i < 4; i++) {
            int p   = tid + i * 256;
            int arr = p >> 9;
            int rem = p & 511;
            int row = rem >> 2;
            int c   = (rem & 3) * 8;
            const __half* src = arr ? Alg : Ahg;
            cp_async16(smem_u32(base + arr * G_A + row * ASTR + c),
                       src + (size_t)(bm + row) * D_MODEL + k0 + c);
        }
        #pragma unroll
        for (int i = 0; i < 2; i++) {
            int p   = tid + i * 256;
            int row = p >> 4;
            int c   = (p & 15) * 8;
            cp_async16(smem_u32(base + 2 * G_A + row * BSTR + c),
                       W + (size_t)(k0 + row) * D_MODEL + bn + c);
        }
    };

    load_tile(0, 0); cp_commit();
    load_tile(1, 1); cp_commit();

    for (int kt = 0; kt < G_NK; kt++) {
        const int s = kt & 1;
        if (kt == G_NK - 1) cp_wait<0>(); else cp_wait<1>();
        __syncthreads();
        __half* sAh = dsm + s * G_ST;
        __half* sAl = sAh + G_A;
        __half* sB  = sAh + 2 * G_A;

        #pragma unroll
        for (int ks = 0; ks < 2; ks++) {
            uint32_t ah[4][4], al[4][4], bh[4][2];
            #pragma unroll
            for (int i = 0; i < 4; i++) {
                uint32_t ad = smem_u32(sAh + (wm + i * 16 + lm_r) * ASTR + ks * 16 + lm_c);
                ldsm_x4(ad, ah[i][0], ah[i][1], ah[i][2], ah[i][3]);
                uint32_t ad2 = smem_u32(sAl + (wm + i * 16 + lm_r) * ASTR + ks * 16 + lm_c);
                ldsm_x4(ad2, al[i][0], al[i][1], al[i][2], al[i][3]);
            }
            #pragma unroll
            for (int j2 = 0; j2 < 2; j2++) {
                uint32_t bd = smem_u32(sB + (ks * 16 + lm_r) * BSTR + wn + j2 * 16 + lm_c);
                ldsm_x4_t(bd, bh[2*j2][0], bh[2*j2][1], bh[2*j2+1][0], bh[2*j2+1][1]);
            }
            #pragma unroll
            for (int i = 0; i < 4; i++)
                #pragma unroll
                for (int j = 0; j < 4; j++) mma_h(acc[i][j], ah[i], bh[j]);
            #pragma unroll
            for (int i = 0; i < 4; i++)
                #pragma unroll
                for (int j = 0; j < 4; j++) mma_h(acc[i][j], al[i], bh[j]);
        }
        __syncthreads();
        if (kt + 2 < G_NK) load_tile(kt + 2, s);
        cp_commit();
    }

    #pragma unroll
    for (int i = 0; i < 4; i++) {
        int r0 = bm + wm + i * 16 + g;
        #pragma unroll
        for (int j = 0; j < 4; j++) {
            int c = bn + wn + j * 8 + tig * 2;
            float b0 = bias[c], b1 = bias[c + 1];
            float x0 = acc[i][j][0] + b0, y0 = acc[i][j][1] + b1;
            float x1 = acc[i][j][2] + b0, y1 = acc[i][j][3] + b1;
            size_t a0 = (size_t)r0 * D_MODEL + c;
            size_t a1 = (size_t)(r0 + 8) * D_MODEL + c;
            if (!PROJ) {
                *(float2*)&Cf[a0] = make_float2(x0, y0);
                *(float2*)&Cf[a1] = make_float2(x1, y1);
            } else if (z == 0) {
                uint32_t h0, l0, h1, l1;
                split_pack_h(x0, y0, h0, l0);
                split_pack_h(x1, y1, h1, l1);
                *(uint32_t*)&Qh[a0] = h0; *(uint32_t*)&Ql[a0] = l0;
                *(uint32_t*)&Qh[a1] = h1; *(uint32_t*)&Ql[a1] = l1;
            } else if (z == 1) {
                *(uint32_t*)&Kh[a0] = pack_h(x0, y0);
                *(uint32_t*)&Kh[a1] = pack_h(x1, y1);
            } else {
                *(uint32_t*)&Vh[a0] = pack_h(x0, y0);
                *(uint32_t*)&Vh[a1] = pack_h(x1, y1);
            }
        }
    }
}

// ---------------------------------------------------------------------------
// Flash attention, fp16. Q hi+lo; K/V single fp16; P single fp16.
// K b-fragments via ldmatrix.x4; exp2f softmax. 2-stage cp.async K/V.
// ---------------------------------------------------------------------------
#define QBLK 128
#define KBLK 64
#define KSTR 72
#define KV_ARR (KBLK * KSTR)
#define KV_ST  (2 * KV_ARR)
#define A_SMEMB (2 * KV_ST * 2)
#define A_NK (SEQ / KBLK)

__global__ __launch_bounds__(256, 2)
void attn_h(const __half* __restrict__ Qhg, const __half* __restrict__ Qlg,
            const __half* __restrict__ Khg, const __half* __restrict__ Vhg,
            __half* __restrict__ Ohg, __half* __restrict__ Olg)
{
    extern __shared__ __align__(16) __half dsm[];

    const int tid  = threadIdx.x;
    const int lane = tid & 31;
    const int warp = tid >> 5;
    const int g    = lane >> 2;
    const int tig  = lane & 3;
    const int lm_r = (lane & 7) + ((lane >> 3) & 1) * 8;
    const int lm_c = (lane >> 4) * 8;
    // K-fragment ldmatrix lane mapping: tile = lane>>3 within each x4
    const int kf_key = ((lane >> 4) & 1) * 8 + (lane & 7);  // key offset in 16-group
    const int kf_col = ((lane >> 3) & 1) * 8;               // k-column offset

    const int b  = blockIdx.z;
    const int h  = blockIdx.y;
    const int q0 = blockIdx.x * QBLK;
    const size_t qbase = ((size_t)(b * SEQ + q0)) * D_MODEL + h * DHEAD;
    const float SC = 0.125f * 1.44269504088896f;   // 1/sqrt(64) * log2(e)

    // ---- Q staging then register fragments ----
    #pragma unroll
    for (int i = 0; i < 8; i++) {
        int idx = tid + i * 256;
        int arr = idx >> 10;
        int rem = idx & 1023;
        int row = rem >> 3;
        int c   = (rem & 7) * 8;
        const __half* src = arr ? Qlg : Qhg;
        *(uint4*)&dsm[arr * 9216 + row * KSTR + c] =
            *(const uint4*)&src[qbase + (size_t)row * D_MODEL + c];
    }
    __syncthreads();
    uint32_t qh[4][4], ql[4][4];
    #pragma unroll
    for (int ks = 0; ks < 4; ks++) {
        uint32_t ad = smem_u32(&dsm[(warp * 16 + lm_r) * KSTR + ks * 16 + lm_c]);
        ldsm_x4(ad, qh[ks][0], qh[ks][1], qh[ks][2], qh[ks][3]);
        uint32_t ad2 = smem_u32(&dsm[9216 + (warp * 16 + lm_r) * KSTR + ks * 16 + lm_c]);
        ldsm_x4(ad2, ql[ks][0], ql[ks][1], ql[ks][2], ql[ks][3]);
    }
    __syncthreads();

    auto prefetch = [&](int kt, int s) {
        __half* base = dsm + s * KV_ST;
        const size_t gk = ((size_t)(b * SEQ + kt * KBLK)) * D_MODEL + h * DHEAD;
        #pragma unroll
        for (int i = 0; i < 4; i++) {
            int idx = tid + i * 256;
            int arr = idx >> 9;
            int rem = idx & 511;
            int row = rem >> 3;
            int c   = (rem & 7) * 8;
            const __half* src = arr ? Vhg : Khg;
            cp_async16(smem_u32(base + arr * KV_ARR + row * KSTR + c),
                       src + gk + (size_t)row * D_MODEL + c);
        }
    };

    float out[8][4];
    #pragma unroll
    for (int j = 0; j < 8; j++)
        #pragma unroll
        for (int t = 0; t < 4; t++) out[j][t] = 0.0f;
    float mrow[2] = {-INFINITY, -INFINITY};   // in log2 units
    float lrow[2] = {0.0f, 0.0f};

    prefetch(0, 0); cp_commit();
    prefetch(1, 1); cp_commit();

    for (int kt = 0; kt < A_NK; kt++) {
        const int s = kt & 1;
        if (kt == A_NK - 1) cp_wait<0>(); else cp_wait<1>();
        __syncthreads();
        __half* sK = dsm + s * KV_ST;
        __half* sV = sK + KV_ARR;

        // ---- QK^T (qh.k + ql.k); K b-frags via ldmatrix ----
        float sc[8][4];
        #pragma unroll
        for (int j = 0; j < 8; j++)
            #pragma unroll
            for (int t = 0; t < 4; t++) sc[j][t] = 0.0f;

        #pragma unroll
        for (int ks = 0; ks < 4; ks++) {
            uint32_t bh[8][2];
            const int dd = ks * 16 + kf_col;
            #pragma unroll
            for (int jp = 0; jp < 4; jp++) {
                uint32_t ad = smem_u32(sK + (jp * 16 + kf_key) * KSTR + dd);
                ldsm_x4(ad, bh[2*jp][0], bh[2*jp][1], bh[2*jp+1][0], bh[2*jp+1][1]);
            }
            #pragma unroll
            for (int j = 0; j < 8; j++) mma_h(sc[j], qh[ks], bh[j]);
            #pragma unroll
            for (int j = 0; j < 8; j++) mma_h(sc[j], ql[ks], bh[j]);
        }
        #pragma unroll
        for (int j = 0; j < 8; j++)
            #pragma unroll
            for (int t = 0; t < 4; t++) sc[j][t] *= SC;   // scores in log2 units

        // ---- online softmax (exp2) ----
        #pragma unroll
        for (int r = 0; r < 2; r++) {
            float mx = -INFINITY;
            #pragma unroll
            for (int j = 0; j < 8; j++) {
                mx = fmaxf(mx, sc[j][2 * r]);
                mx = fmaxf(mx, sc[j][2 * r + 1]);
            }
            mx = fmaxf(mx, __shfl_xor_sync(0xFFFFFFFFu, mx, 1));
            mx = fmaxf(mx, __shfl_xor_sync(0xFFFFFFFFu, mx, 2));
            float newm = fmaxf(mrow[r], mx);
            float corr = exp2f(mrow[r] - newm);
            mrow[r] = newm;
            float lsum = 0.0f;
            #pragma unroll
            for (int j = 0; j < 8; j++) {
                float e0 = exp2f(sc[j][2 * r]     - newm);
                float e1 = exp2f(sc[j][2 * r + 1] - newm);
                sc[j][2 * r] = e0; sc[j][2 * r + 1] = e1;
                lsum += e0 + e1;
                out[j][2 * r]     *= corr;
                out[j][2 * r + 1] *= corr;
            }
            lrow[r] = lrow[r] * corr + lsum;
        }

        // ---- P @ V (single-pass fp16 P) ----
        #pragma unroll
        for (int ss = 0; ss < 4; ss++) {
            uint32_t ph[4];
            ph[0] = pack_h(sc[2 * ss][0],     sc[2 * ss][1]);
            ph[1] = pack_h(sc[2 * ss][2],     sc[2 * ss][3]);
            ph[2] = pack_h(sc[2 * ss + 1][0], sc[2 * ss + 1][1]);
            ph[3] = pack_h(sc[2 * ss + 1][2], sc[2 * ss + 1][3]);

            uint32_t vh[8][2];
            #pragma unroll
            for (int j2 = 0; j2 < 4; j2++) {
                uint32_t vd = smem_u32(sV + (ss * 16 + lm_r) * KSTR + j2 * 16 + lm_c);
                ldsm_x4_t(vd, vh[2*j2][0], vh[2*j2][1], vh[2*j2+1][0], vh[2*j2+1][1]);
            }
            #pragma unroll
            for (int j = 0; j < 8; j++) mma_h(out[j], ph, vh[j]);
        }
        __syncthreads();
        if (kt + 2 < A_NK) prefetch(kt + 2, s);
        cp_commit();
    }

    // ---- finalize ----
    #pragma unroll
    for (int r = 0; r < 2; r++) {
        lrow[r] += __shfl_xor_sync(0xFFFFFFFFu, lrow[r], 1);
        lrow[r] += __shfl_xor_sync(0xFFFFFFFFu, lrow[r], 2);
    }
    const float inv0 = 1.0f / lrow[0];
    const float inv1 = 1.0f / lrow[1];
    const int row0 = q0 + warp * 16 + g;
    #pragma unroll
    for (int j = 0; j < 8; j++) {
        int d = j * 8 + tig * 2;
        size_t addr = ((size_t)(b * SEQ + row0)) * D_MODEL + h * DHEAD + d;
        uint32_t h0, l0, h1, l1;
        split_pack_h(out[j][0] * inv0, out[j][1] * inv0, h0, l0);
        split_pack_h(out[j][2] * inv1, out[j][3] * inv1, h1, l1);
        *(uint32_t*)&Ohg[addr]               = h0;
        *(uint32_t*)&Olg[addr]               = l0;
        *(uint32_t*)&Ohg[addr + 8 * D_MODEL] = h1;
        *(uint32_t*)&Olg[addr + 8 * D_MODEL] = l1;
    }
}

// ---------------------------------------------------------------------------
// Launch
// ---------------------------------------------------------------------------
extern "C" void kernel_launch(void* const* d_in, const int* in_sizes, int n_in,
                              void* d_out, int out_size)
{
    const float* queries = (const float*)d_in[0];
    const float* keys    = (const float*)d_in[1];
    const float* values  = (const float*)d_in[2];
    const float* Wq      = (const float*)d_in[3];
    const float* bq      = (const float*)d_in[4];
    const float* Wk      = (const float*)d_in[5];
    const float* bk      = (const float*)d_in[6];
    const float* Wv      = (const float*)d_in[7];
    const float* bv      = (const float*)d_in[8];
    const float* Wo      = (const float*)d_in[9];
    const float* bo      = (const float*)d_in[10];
    float* out = (float*)d_out;

    __half *wq, *wk, *wv, *wo, *qh, *ql, *kh, *vh, *oh, *ol;
    __half *xh0, *xl0, *xh1, *xl1, *xh2, *xl2;
    cudaGetSymbolAddress((void**)&wq, g_wq);
    cudaGetSymbolAddress((void**)&wk, g_wk);
    cudaGetSymbolAddress((void**)&wv, g_wv);
    cudaGetSymbolAddress((void**)&wo, g_wo);
    cudaGetSymbolAddress((void**)&qh, g_qh);
    cudaGetSymbolAddress((void**)&ql, g_ql);
    cudaGetSymbolAddress((void**)&kh, g_kh);
    cudaGetSymbolAddress((void**)&vh, g_vh);
    cudaGetSymbolAddress((void**)&oh, g_oh);
    cudaGetSymbolAddress((void**)&ol, g_ol);
    {
        __half* base;
        cudaGetSymbolAddress((void**)&base, g_xh);
        xh0 = base; xh1 = base + NACT; xh2 = base + 2 * NACT;
        cudaGetSymbolAddress((void**)&base, g_xl);
        xl0 = base; xl1 = base + NACT; xl2 = base + 2 * NACT;
    }

    cudaFuncSetAttribute(gemm_u<true>,  cudaFuncAttributeMaxDynamicSharedMemorySize, G_SMEMB);
    cudaFuncSetAttribute(gemm_u<false>, cudaFuncAttributeMaxDynamicSharedMemorySize, G_SMEMB);
    cudaFuncSetAttribute(attn_h,        cudaFuncAttributeMaxDynamicSharedMemorySize, A_SMEMB);

    round_w4<<<dim3((unsigned)(NW / (256 * 8)), 4), 256>>>(Wq, Wk, Wv, Wo, wq, wk, wv, wo);
    split_act3<<<dim3((unsigned)(NACT / (256 * 4)), 3), 256>>>(
        queries, keys, values, xh0, xl0, xh1, xl1, xh2, xl2);

    gemm_u<true><<<dim3(D_MODEL / 128, MROWS / 128, 3), 256, G_SMEMB>>>(
        xh0, xl0, xh1, xl1, xh2, xl2, wq, wk, wv, bq, bk, bv,
        qh, ql, kh, vh, nullptr);

    attn_h<<<dim3(SEQ / QBLK, NH, BATCH), 256, A_SMEMB>>>(qh, ql, kh, vh, oh, ol);

    gemm_u<false><<<dim3(D_MODEL / 128, MROWS / 128, 1), 256, G_SMEMB>>>(
        oh, ol, nullptr, nullptr, nullptr, nullptr, wo, nullptr, nullptr,
        bo, nullptr, nullptr, nullptr, nullptr, nullptr, nullptr, out);
}

// round 9
// speedup vs baseline: 1.7231x; 1.0868x over previous
#include <cuda_runtime.h>
#include <cuda_fp16.h>
#include <math.h>
#include <stdint.h>

#define D_MODEL 1024
#define NH      16
#define DHEAD   64
#define BATCH   4
#define SEQ     1024
#define MROWS   (BATCH * SEQ)   // 4096

// ---------------------------------------------------------------------------
// Scratch (static device globals). fp16.
// ---------------------------------------------------------------------------
#define NACT ((size_t)MROWS * D_MODEL)   // 4M
#define NW   ((size_t)D_MODEL * D_MODEL) // 1M
__device__ __half g_wq[NW], g_wk[NW], g_wv[NW], g_wo[NW];   // [K,N] fp16
__device__ __half g_xh[3][NACT], g_xl[3][NACT];             // split activations
__device__ __half g_qh[NACT], g_ql[NACT];                   // Q split
__device__ __half g_kh[NACT];                               // K fp16
__device__ __half g_vh[NACT];                               // V fp16
__device__ __half g_oh[NACT];                               // attn out (single fp16)

// ---------------------------------------------------------------------------
// Helpers
// ---------------------------------------------------------------------------
__device__ __forceinline__ uint32_t smem_u32(const void* p) {
    return (uint32_t)__cvta_generic_to_shared(p);
}
__device__ __forceinline__ void cp_async16(uint32_t dst, const void* src) {
    asm volatile("cp.async.cg.shared.global [%0], [%1], 16;" :: "r"(dst), "l"(src));
}
__device__ __forceinline__ void cp_commit() {
    asm volatile("cp.async.commit_group;");
}
template <int N>
__device__ __forceinline__ void cp_wait() {
    asm volatile("cp.async.wait_group %0;" :: "n"(N));
}
__device__ __forceinline__ void ldsm_x4(uint32_t addr, uint32_t& r0, uint32_t& r1,
                                        uint32_t& r2, uint32_t& r3) {
    asm volatile("ldmatrix.sync.aligned.m8n8.x4.shared.b16 {%0,%1,%2,%3}, [%4];"
                 : "=r"(r0), "=r"(r1), "=r"(r2), "=r"(r3) : "r"(addr));
}
__device__ __forceinline__ void ldsm_x4_t(uint32_t addr, uint32_t& r0, uint32_t& r1,
                                          uint32_t& r2, uint32_t& r3) {
    asm volatile("ldmatrix.sync.aligned.m8n8.x4.trans.shared.b16 {%0,%1,%2,%3}, [%4];"
                 : "=r"(r0), "=r"(r1), "=r"(r2), "=r"(r3) : "r"(addr));
}
__device__ __forceinline__ void mma_h(float c[4], const uint32_t a[4], const uint32_t b[2]) {
    asm volatile(
        "mma.sync.aligned.m16n8k16.row.col.f32.f16.f16.f32 "
        "{%0,%1,%2,%3}, {%4,%5,%6,%7}, {%8,%9}, {%0,%1,%2,%3};"
        : "+f"(c[0]), "+f"(c[1]), "+f"(c[2]), "+f"(c[3])
        : "r"(a[0]), "r"(a[1]), "r"(a[2]), "r"(a[3]), "r"(b[0]), "r"(b[1]));
}
__device__ __forceinline__ void split_pack_h(float x, float y, uint32_t& hi, uint32_t& lo) {
    __half xh = __float2half_rn(x);
    __half yh = __float2half_rn(y);
    __half2 h2; h2.x = xh; h2.y = yh;
    hi = *reinterpret_cast<uint32_t*>(&h2);
    float xl = x - __half2float(xh);
    float yl = y - __half2float(yh);
    __half2 l2 = __floats2half2_rn(xl, yl);
    lo = *reinterpret_cast<uint32_t*>(&l2);
}
__device__ __forceinline__ uint32_t pack_h(float x, float y) {
    __half2 h2; h2.x = __float2half_rn(x); h2.y = __float2half_rn(y);
    return *reinterpret_cast<uint32_t*>(&h2);
}

// ---------------------------------------------------------------------------
// Preprocessing: round 4 weights; split 3 activations.
// ---------------------------------------------------------------------------
__global__ __launch_bounds__(256)
void round_w4(const float* __restrict__ w0, const float* __restrict__ w1,
              const float* __restrict__ w2, const float* __restrict__ w3,
              __half* __restrict__ o0, __half* __restrict__ o1,
              __half* __restrict__ o2, __half* __restrict__ o3)
{
    const float* src = (blockIdx.y == 0) ? w0 : (blockIdx.y == 1) ? w1
                     : (blockIdx.y == 2) ? w2 : w3;
    __half* dst = (blockIdx.y == 0) ? o0 : (blockIdx.y == 1) ? o1
                : (blockIdx.y == 2) ? o2 : o3;
    size_t i = ((size_t)blockIdx.x * 256 + threadIdx.x) * 8;
    float4 a = *(const float4*)&src[i];
    float4 b = *(const float4*)&src[i + 4];
    uint4 o;
    o.x = pack_h(a.x, a.y); o.y = pack_h(a.z, a.w);
    o.z = pack_h(b.x, b.y); o.w = pack_h(b.z, b.w);
    *(uint4*)&dst[i] = o;
}

__global__ __launch_bounds__(256)
void split_act3(const float* __restrict__ a0, const float* __restrict__ a1,
                const float* __restrict__ a2,
                __half* __restrict__ h0, __half* __restrict__ l0_,
                __half* __restrict__ h1, __half* __restrict__ l1_,
                __half* __restrict__ h2, __half* __restrict__ l2_)
{
    const float* src = (blockIdx.y == 0) ? a0 : (blockIdx.y == 1) ? a1 : a2;
    __half* dh = (blockIdx.y == 0) ? h0 : (blockIdx.y == 1) ? h1 : h2;
    __half* dl = (blockIdx.y == 0) ? l0_ : (blockIdx.y == 1) ? l1_ : l2_;
    size_t i = ((size_t)blockIdx.x * 256 + threadIdx.x) * 4;
    float4 v = *(const float4*)&src[i];
    uint32_t ha, la, hb, lb;
    split_pack_h(v.x, v.y, ha, la);
    split_pack_h(v.z, v.w, hb, lb);
    *(uint2*)&dh[i] = make_uint2(ha, hb);
    *(uint2*)&dl[i] = make_uint2(la, lb);
}

// ---------------------------------------------------------------------------
// Unified GEMM: C = A @ W + bias, 2-stage cp.async.
// ALO: A has a lo-residual array (2-pass). PROJ: fused QKV epilogues.
// ---------------------------------------------------------------------------
#define GBK  32
#define ASTR 40
#define BSTR 136
#define G_A  (128 * ASTR)
#define G_B  (GBK * BSTR)
#define G_ST (2 * G_A + G_B)
#define G_SMEMB (2 * G_ST * 2)
#define G_NK (D_MODEL / GBK)

template <bool PROJ, bool ALO>
__global__ __launch_bounds__(256, 2)
void gemm_u(const __half* __restrict__ Ah0, const __half* __restrict__ Al0,
            const __half* __restrict__ Ah1, const __half* __restrict__ Al1,
            const __half* __restrict__ Ah2, const __half* __restrict__ Al2,
            const __half* __restrict__ W0, const __half* __restrict__ W1,
            const __half* __restrict__ W2,
            const float* __restrict__ bi0, const float* __restrict__ bi1,
            const float* __restrict__ bi2,
            __half* __restrict__ Qh, __half* __restrict__ Ql,
            __half* __restrict__ Kh, __half* __restrict__ Vh,
            float* __restrict__ Cf)
{
    extern __shared__ __align__(16) __half dsm[];

    const int z = PROJ ? blockIdx.z : 0;
    const __half* Ahg  = (z == 0) ? Ah0 : (z == 1) ? Ah1 : Ah2;
    const __half* Alg  = (z == 0) ? Al0 : (z == 1) ? Al1 : Al2;
    const __half* W    = (z == 0) ? W0  : (z == 1) ? W1  : W2;
    const float*  bias = (z == 0) ? bi0 : (z == 1) ? bi1 : bi2;

    const int tid  = threadIdx.x;
    const int lane = tid & 31;
    const int warp = tid >> 5;
    const int g    = lane >> 2;
    const int tig  = lane & 3;
    const int wm   = (warp >> 2) * 64;
    const int wn   = (warp & 3) * 32;
    const int bm   = blockIdx.y * 128;
    const int bn   = blockIdx.x * 128;
    const int lm_r = (lane & 7) + ((lane >> 3) & 1) * 8;
    const int lm_c = (lane >> 4) * 8;

    float acc[4][4][4];
    #pragma unroll
    for (int i = 0; i < 4; i++)
        #pragma unroll
        for (int j = 0; j < 4; j++)
            #pragma unroll
            for (int t = 0; t < 4; t++) acc[i][j][t] = 0.0f;

    auto load_tile = [&](int kt, int s) {
        __half* base = dsm + s * G_ST;
        const int k0 = kt * GBK;
        #pragma unroll
        for (int i = 0; i < (ALO ? 4 : 2); i++) {
            int p   = tid + i * 256;
            int arr = ALO ? (p >> 9) : 0;
            int rem = ALO ? (p & 511) : p;
            int row = rem >> 2;
            int c   = (rem & 3) * 8;
            const __half* src = arr ? Alg : Ahg;
            cp_async16(smem_u32(base + arr * G_A + row * ASTR + c),
                       src + (size_t)(bm + row) * D_MODEL + k0 + c);
        }
        #pragma unroll
        for (int i = 0; i < 2; i++) {
            int p   = tid + i * 256;
            int row = p >> 4;
            int c   = (p & 15) * 8;
            cp_async16(smem_u32(base + 2 * G_A + row * BSTR + c),
                       W + (size_t)(k0 + row) * D_MODEL + bn + c);
        }
    };

    load_tile(0, 0); cp_commit();
    load_tile(1, 1); cp_commit();

    for (int kt = 0; kt < G_NK; kt++) {
        const int s = kt & 1;
        if (kt == G_NK - 1) cp_wait<0>(); else cp_wait<1>();
        __syncthreads();
        __half* sAh = dsm + s * G_ST;
        __half* sAl = sAh + G_A;
        __half* sB  = sAh + 2 * G_A;

        #pragma unroll
        for (int ks = 0; ks < 2; ks++) {
            uint32_t ah[4][4], al[4][4], bh[4][2];
            #pragma unroll
            for (int i = 0; i < 4; i++) {
                uint32_t ad = smem_u32(sAh + (wm + i * 16 + lm_r) * ASTR + ks * 16 + lm_c);
                ldsm_x4(ad, ah[i][0], ah[i][1], ah[i][2], ah[i][3]);
                if (ALO) {
                    uint32_t ad2 = smem_u32(sAl + (wm + i * 16 + lm_r) * ASTR + ks * 16 + lm_c);
                    ldsm_x4(ad2, al[i][0], al[i][1], al[i][2], al[i][3]);
                }
            }
            #pragma unroll
            for (int j2 = 0; j2 < 2; j2++) {
                uint32_t bd = smem_u32(sB + (ks * 16 + lm_r) * BSTR + wn + j2 * 16 + lm_c);
                ldsm_x4_t(bd, bh[2*j2][0], bh[2*j2][1], bh[2*j2+1][0], bh[2*j2+1][1]);
            }
            #pragma unroll
            for (int i = 0; i < 4; i++)
                #pragma unroll
                for (int j = 0; j < 4; j++) mma_h(acc[i][j], ah[i], bh[j]);
            if (ALO) {
                #pragma unroll
                for (int i = 0; i < 4; i++)
                    #pragma unroll
                    for (int j = 0; j < 4; j++) mma_h(acc[i][j], al[i], bh[j]);
            }
        }
        __syncthreads();
        if (kt + 2 < G_NK) load_tile(kt + 2, s);
        cp_commit();
    }

    #pragma unroll
    for (int i = 0; i < 4; i++) {
        int r0 = bm + wm + i * 16 + g;
        #pragma unroll
        for (int j = 0; j < 4; j++) {
            int c = bn + wn + j * 8 + tig * 2;
            float b0 = bias[c], b1 = bias[c + 1];
            float x0 = acc[i][j][0] + b0, y0 = acc[i][j][1] + b1;
            float x1 = acc[i][j][2] + b0, y1 = acc[i][j][3] + b1;
            size_t a0 = (size_t)r0 * D_MODEL + c;
            size_t a1 = (size_t)(r0 + 8) * D_MODEL + c;
            if (!PROJ) {
                *(float2*)&Cf[a0] = make_float2(x0, y0);
                *(float2*)&Cf[a1] = make_float2(x1, y1);
            } else if (z == 0) {
                uint32_t h0, l0, h1, l1;
                split_pack_h(x0, y0, h0, l0);
                split_pack_h(x1, y1, h1, l1);
                *(uint32_t*)&Qh[a0] = h0; *(uint32_t*)&Ql[a0] = l0;
                *(uint32_t*)&Qh[a1] = h1; *(uint32_t*)&Ql[a1] = l1;
            } else if (z == 1) {
                *(uint32_t*)&Kh[a0] = pack_h(x0, y0);
                *(uint32_t*)&Kh[a1] = pack_h(x1, y1);
            } else {
                *(uint32_t*)&Vh[a0] = pack_h(x0, y0);
                *(uint32_t*)&Vh[a1] = pack_h(x1, y1);
            }
        }
    }
}

// ---------------------------------------------------------------------------
// Flash attention, fp16. Q hi+lo; K/V/P/O single fp16.
// FMA-fused exp2 softmax with conditional rescale. 2-stage cp.async K/V.
// ---------------------------------------------------------------------------
#define QBLK 128
#define KBLK 64
#define KSTR 72
#define KV_ARR (KBLK * KSTR)
#define KV_ST  (2 * KV_ARR)
#define A_SMEMB (2 * KV_ST * 2)
#define A_NK (SEQ / KBLK)

__global__ __launch_bounds__(256, 2)
void attn_h(const __half* __restrict__ Qhg, const __half* __restrict__ Qlg,
            const __half* __restrict__ Khg, const __half* __restrict__ Vhg,
            __half* __restrict__ Ohg)
{
    extern __shared__ __align__(16) __half dsm[];

    const int tid  = threadIdx.x;
    const int lane = tid & 31;
    const int warp = tid >> 5;
    const int g    = lane >> 2;
    const int tig  = lane & 3;
    const int lm_r = (lane & 7) + ((lane >> 3) & 1) * 8;
    const int lm_c = (lane >> 4) * 8;
    const int kf_key = ((lane >> 4) & 1) * 8 + (lane & 7);
    const int kf_col = ((lane >> 3) & 1) * 8;

    const int b  = blockIdx.z;
    const int h  = blockIdx.y;
    const int q0 = blockIdx.x * QBLK;
    const size_t qbase = ((size_t)(b * SEQ + q0)) * D_MODEL + h * DHEAD;
    const float SC = 0.125f * 1.44269504088896f;   // 1/sqrt(64) * log2(e)

    // ---- Q staging then register fragments ----
    #pragma unroll
    for (int i = 0; i < 8; i++) {
        int idx = tid + i * 256;
        int arr = idx >> 10;
        int rem = idx & 1023;
        int row = rem >> 3;
        int c   = (rem & 7) * 8;
        const __half* src = arr ? Qlg : Qhg;
        *(uint4*)&dsm[arr * 9216 + row * KSTR + c] =
            *(const uint4*)&src[qbase + (size_t)row * D_MODEL + c];
    }
    __syncthreads();
    uint32_t qh[4][4], ql[4][4];
    #pragma unroll
    for (int ks = 0; ks < 4; ks++) {
        uint32_t ad = smem_u32(&dsm[(warp * 16 + lm_r) * KSTR + ks * 16 + lm_c]);
        ldsm_x4(ad, qh[ks][0], qh[ks][1], qh[ks][2], qh[ks][3]);
        uint32_t ad2 = smem_u32(&dsm[9216 + (warp * 16 + lm_r) * KSTR + ks * 16 + lm_c]);
        ldsm_x4(ad2, ql[ks][0], ql[ks][1], ql[ks][2], ql[ks][3]);
    }
    __syncthreads();

    auto prefetch = [&](int kt, int s) {
        __half* base = dsm + s * KV_ST;
        const size_t gk = ((size_t)(b * SEQ + kt * KBLK)) * D_MODEL + h * DHEAD;
        #pragma unroll
        for (int i = 0; i < 4; i++) {
            int idx = tid + i * 256;
            int arr = idx >> 9;
            int rem = idx & 511;
            int row = rem >> 3;
            int c   = (rem & 7) * 8;
            const __half* src = arr ? Vhg : Khg;
            cp_async16(smem_u32(base + arr * KV_ARR + row * KSTR + c),
                       src + gk + (size_t)row * D_MODEL + c);
        }
    };

    float out[8][4];
    #pragma unroll
    for (int j = 0; j < 8; j++)
        #pragma unroll
        for (int t = 0; t < 4; t++) out[j][t] = 0.0f;
    float mrow[2] = {-INFINITY, -INFINITY};   // log2 units
    float lrow[2] = {0.0f, 0.0f};

    prefetch(0, 0); cp_commit();
    prefetch(1, 1); cp_commit();

    for (int kt = 0; kt < A_NK; kt++) {
        const int s = kt & 1;
        if (kt == A_NK - 1) cp_wait<0>(); else cp_wait<1>();
        __syncthreads();
        __half* sK = dsm + s * KV_ST;
        __half* sV = sK + KV_ARR;

        // ---- QK^T (raw scores, no pre-scale) ----
        float sc[8][4];
        #pragma unroll
        for (int j = 0; j < 8; j++)
            #pragma unroll
            for (int t = 0; t < 4; t++) sc[j][t] = 0.0f;

        #pragma unroll
        for (int ks = 0; ks < 4; ks++) {
            uint32_t bh[8][2];
            const int dd = ks * 16 + kf_col;
            #pragma unroll
            for (int jp = 0; jp < 4; jp++) {
                uint32_t ad = smem_u32(sK + (jp * 16 + kf_key) * KSTR + dd);
                ldsm_x4(ad, bh[2*jp][0], bh[2*jp][1], bh[2*jp+1][0], bh[2*jp+1][1]);
            }
            #pragma unroll
            for (int j = 0; j < 8; j++) mma_h(sc[j], qh[ks], bh[j]);
            #pragma unroll
            for (int j = 0; j < 8; j++) mma_h(sc[j], ql[ks], bh[j]);
        }

        // ---- online softmax: max on raw, exp2(s*SC - m) via FMA ----
        #pragma unroll
        for (int r = 0; r < 2; r++) {
            float mx = -INFINITY;
            #pragma unroll
            for (int j = 0; j < 8; j++) {
                mx = fmaxf(mx, sc[j][2 * r]);
                mx = fmaxf(mx, sc[j][2 * r + 1]);
            }
            mx = fmaxf(mx, __shfl_xor_sync(0xFFFFFFFFu, mx, 1));
            mx = fmaxf(mx, __shfl_xor_sync(0xFFFFFFFFu, mx, 2));
            const float mx2 = mx * SC;               // log2 units
            float lsum = 0.0f;
            if (mx2 > mrow[r]) {
                const float corr = exp2f(mrow[r] - mx2);   // 0 on first tile
                mrow[r] = mx2;
                #pragma unroll
                for (int j = 0; j < 8; j++) {
                    out[j][2 * r]     *= corr;
                    out[j][2 * r + 1] *= corr;
                }
                lrow[r] *= corr;
            }
            const float nm = mrow[r];
            #pragma unroll
            for (int j = 0; j < 8; j++) {
                float e0 = exp2f(fmaf(sc[j][2 * r],     SC, -nm));
                float e1 = exp2f(fmaf(sc[j][2 * r + 1], SC, -nm));
                sc[j][2 * r] = e0; sc[j][2 * r + 1] = e1;
                lsum += e0 + e1;
            }
            lrow[r] += lsum;
        }

        // ---- P @ V (single-pass fp16 P) ----
        #pragma unroll
        for (int ss = 0; ss < 4; ss++) {
            uint32_t ph[4];
            ph[0] = pack_h(sc[2 * ss][0],     sc[2 * ss][1]);
            ph[1] = pack_h(sc[2 * ss][2],     sc[2 * ss][3]);
            ph[2] = pack_h(sc[2 * ss + 1][0], sc[2 * ss + 1][1]);
            ph[3] = pack_h(sc[2 * ss + 1][2], sc[2 * ss + 1][3]);

            uint32_t vh[8][2];
            #pragma unroll
            for (int j2 = 0; j2 < 4; j2++) {
                uint32_t vd = smem_u32(sV + (ss * 16 + lm_r) * KSTR + j2 * 16 + lm_c);
                ldsm_x4_t(vd, vh[2*j2][0], vh[2*j2][1], vh[2*j2+1][0], vh[2*j2+1][1]);
            }
            #pragma unroll
            for (int j = 0; j < 8; j++) mma_h(out[j], ph, vh[j]);
        }
        __syncthreads();
        if (kt + 2 < A_NK) prefetch(kt + 2, s);
        cp_commit();
    }

    // ---- finalize: single fp16 O ----
    #pragma unroll
    for (int r = 0; r < 2; r++) {
        lrow[r] += __shfl_xor_sync(0xFFFFFFFFu, lrow[r], 1);
        lrow[r] += __shfl_xor_sync(0xFFFFFFFFu, lrow[r], 2);
    }
    const float inv0 = 1.0f / lrow[0];
    const float inv1 = 1.0f / lrow[1];
    const int row0 = q0 + warp * 16 + g;
    #pragma unroll
    for (int j = 0; j < 8; j++) {
        int d = j * 8 + tig * 2;
        size_t addr = ((size_t)(b * SEQ + row0)) * D_MODEL + h * DHEAD + d;
        *(uint32_t*)&Ohg[addr]               = pack_h(out[j][0] * inv0, out[j][1] * inv0);
        *(uint32_t*)&Ohg[addr + 8 * D_MODEL] = pack_h(out[j][2] * inv1, out[j][3] * inv1);
    }
}

// ---------------------------------------------------------------------------
// Launch
// ---------------------------------------------------------------------------
extern "C" void kernel_launch(void* const* d_in, const int* in_sizes, int n_in,
                              void* d_out, int out_size)
{
    const float* queries = (const float*)d_in[0];
    const float* keys    = (const float*)d_in[1];
    const float* values  = (const float*)d_in[2];
    const float* Wq      = (const float*)d_in[3];
    const float* bq      = (const float*)d_in[4];
    const float* Wk      = (const float*)d_in[5];
    const float* bk      = (const float*)d_in[6];
    const float* Wv      = (const float*)d_in[7];
    const float* bv      = (const float*)d_in[8];
    const float* Wo      = (const float*)d_in[9];
    const float* bo      = (const float*)d_in[10];
    float* out = (float*)d_out;

    __half *wq, *wk, *wv, *wo, *qh, *ql, *kh, *vh, *oh;
    __half *xh0, *xl0, *xh1, *xl1, *xh2, *xl2;
    cudaGetSymbolAddress((void**)&wq, g_wq);
    cudaGetSymbolAddress((void**)&wk, g_wk);
    cudaGetSymbolAddress((void**)&wv, g_wv);
    cudaGetSymbolAddress((void**)&wo, g_wo);
    cudaGetSymbolAddress((void**)&qh, g_qh);
    cudaGetSymbolAddress((void**)&ql, g_ql);
    cudaGetSymbolAddress((void**)&kh, g_kh);
    cudaGetSymbolAddress((void**)&vh, g_vh);
    cudaGetSymbolAddress((void**)&oh, g_oh);
    {
        __half* base;
        cudaGetSymbolAddress((void**)&base, g_xh);
        xh0 = base; xh1 = base + NACT; xh2 = base + 2 * NACT;
        cudaGetSymbolAddress((void**)&base, g_xl);
        xl0 = base; xl1 = base + NACT; xl2 = base + 2 * NACT;
    }

    cudaFuncSetAttribute((const void*)gemm_u<true, true>,
                         cudaFuncAttributeMaxDynamicSharedMemorySize, G_SMEMB);
    cudaFuncSetAttribute((const void*)gemm_u<false, false>,
                         cudaFuncAttributeMaxDynamicSharedMemorySize, G_SMEMB);
    cudaFuncSetAttribute((const void*)attn_h,
                         cudaFuncAttributeMaxDynamicSharedMemorySize, A_SMEMB);

    round_w4<<<dim3((unsigned)(NW / (256 * 8)), 4), 256>>>(Wq, Wk, Wv, Wo, wq, wk, wv, wo);
    split_act3<<<dim3((unsigned)(NACT / (256 * 4)), 3), 256>>>(
        queries, keys, values, xh0, xl0, xh1, xl1, xh2, xl2);

    gemm_u<true, true><<<dim3(D_MODEL / 128, MROWS / 128, 3), 256, G_SMEMB>>>(
        xh0, xl0, xh1, xl1, xh2, xl2, wq, wk, wv, bq, bk, bv,
        qh, ql, kh, vh, nullptr);

    attn_h<<<dim3(SEQ / QBLK, NH, BATCH), 256, A_SMEMB>>>(qh, ql, kh, vh, oh);

    gemm_u<false, false><<<dim3(D_MODEL / 128, MROWS / 128, 1), 256, G_SMEMB>>>(
        oh, nullptr, nullptr, nullptr, nullptr, nullptr, wo, nullptr, nullptr,
        bo, nullptr, nullptr, nullptr, nullptr, nullptr, nullptr, out);
}

// round 10
// speedup vs baseline: 2.5384x; 1.4732x over previous
#include <cuda_runtime.h>
#include <cuda_fp16.h>
#include <math.h>
#include <stdint.h>

#define D_MODEL 1024
#define NH      16
#define DHEAD   64
#define BATCH   4
#define SEQ     1024
#define MROWS   (BATCH * SEQ)   // 4096

// ---------------------------------------------------------------------------
// Scratch (static device globals). fp16, all single precision copies.
// ---------------------------------------------------------------------------
#define NACT ((size_t)MROWS * D_MODEL)   // 4M
#define NW   ((size_t)D_MODEL * D_MODEL) // 1M
__device__ __half g_wq[NW], g_wk[NW], g_wv[NW], g_wo[NW];   // [K,N] fp16
__device__ __half g_x[3][NACT];                             // rounded activations
__device__ __half g_qh[NACT];                               // Q fp16
__device__ __half g_kh[NACT];                               // K fp16
__device__ __half g_vh[NACT];                               // V fp16
__device__ __half g_oh[NACT];                               // attn out fp16

// ---------------------------------------------------------------------------
// Helpers
// ---------------------------------------------------------------------------
__device__ __forceinline__ uint32_t smem_u32(const void* p) {
    return (uint32_t)__cvta_generic_to_shared(p);
}
__device__ __forceinline__ void cp_async16(uint32_t dst, const void* src) {
    asm volatile("cp.async.cg.shared.global [%0], [%1], 16;" :: "r"(dst), "l"(src));
}
__device__ __forceinline__ void cp_commit() {
    asm volatile("cp.async.commit_group;");
}
template <int N>
__device__ __forceinline__ void cp_wait() {
    asm volatile("cp.async.wait_group %0;" :: "n"(N));
}
__device__ __forceinline__ void ldsm_x4(uint32_t addr, uint32_t& r0, uint32_t& r1,
                                        uint32_t& r2, uint32_t& r3) {
    asm volatile("ldmatrix.sync.aligned.m8n8.x4.shared.b16 {%0,%1,%2,%3}, [%4];"
                 : "=r"(r0), "=r"(r1), "=r"(r2), "=r"(r3) : "r"(addr));
}
__device__ __forceinline__ void ldsm_x4_t(uint32_t addr, uint32_t& r0, uint32_t& r1,
                                          uint32_t& r2, uint32_t& r3) {
    asm volatile("ldmatrix.sync.aligned.m8n8.x4.trans.shared.b16 {%0,%1,%2,%3}, [%4];"
                 : "=r"(r0), "=r"(r1), "=r"(r2), "=r"(r3) : "r"(addr));
}
__device__ __forceinline__ void mma_h(float c[4], const uint32_t a[4], const uint32_t b[2]) {
    asm volatile(
        "mma.sync.aligned.m16n8k16.row.col.f32.f16.f16.f32 "
        "{%0,%1,%2,%3}, {%4,%5,%6,%7}, {%8,%9}, {%0,%1,%2,%3};"
        : "+f"(c[0]), "+f"(c[1]), "+f"(c[2]), "+f"(c[3])
        : "r"(a[0]), "r"(a[1]), "r"(a[2]), "r"(a[3]), "r"(b[0]), "r"(b[1]));
}
__device__ __forceinline__ uint32_t pack_h(float x, float y) {
    __half2 h2; h2.x = __float2half_rn(x); h2.y = __float2half_rn(y);
    return *reinterpret_cast<uint32_t*>(&h2);
}

// ---------------------------------------------------------------------------
// Preprocessing: round 4 weights + 3 activations to fp16 (blockIdx.y selects).
// ---------------------------------------------------------------------------
__global__ __launch_bounds__(256)
void round7(const float* __restrict__ w0, const float* __restrict__ w1,
            const float* __restrict__ w2, const float* __restrict__ w3,
            const float* __restrict__ a0, const float* __restrict__ a1,
            const float* __restrict__ a2,
            __half* __restrict__ ow0, __half* __restrict__ ow1,
            __half* __restrict__ ow2, __half* __restrict__ ow3,
            __half* __restrict__ oa0, __half* __restrict__ oa1,
            __half* __restrict__ oa2)
{
    const int y = blockIdx.y;
    const float* src;
    __half* dst;
    size_t n;
    switch (y) {
        case 0: src = w0; dst = ow0; n = NW;   break;
        case 1: src = w1; dst = ow1; n = NW;   break;
        case 2: src = w2; dst = ow2; n = NW;   break;
        case 3: src = w3; dst = ow3; n = NW;   break;
        case 4: src = a0; dst = oa0; n = NACT; break;
        case 5: src = a1; dst = oa1; n = NACT; break;
        default: src = a2; dst = oa2; n = NACT; break;
    }
    size_t i = ((size_t)blockIdx.x * 256 + threadIdx.x) * 8;
    if (i >= n) return;
    float4 a = *(const float4*)&src[i];
    float4 b = *(const float4*)&src[i + 4];
    uint4 o;
    o.x = pack_h(a.x, a.y); o.y = pack_h(a.z, a.w);
    o.z = pack_h(b.x, b.y); o.w = pack_h(b.z, b.w);
    *(uint4*)&dst[i] = o;
}

// ---------------------------------------------------------------------------
// Unified single-pass fp16 GEMM: C = A @ W + bias. 128x128x32, 2-stage cp.async.
// PROJ: z in {0,1,2} selects (A,W,bias,dst fp16). !PROJ: fp32 out.
// ---------------------------------------------------------------------------
#define GBK  32
#define ASTR 40
#define BSTR 136
#define G_A  (128 * ASTR)            // 5120 halfs
#define G_B  (GBK * BSTR)            // 4352 halfs
#define G_ST (G_A + G_B)             // 9472 halfs per stage
#define G_SMEMB (2 * G_ST * 2)       // 37888 B
#define G_NK (D_MODEL / GBK)         // 32

template <bool PROJ>
__global__ __launch_bounds__(256, 2)
void gemm_u(const __half* __restrict__ A0, const __half* __restrict__ A1,
            const __half* __restrict__ A2,
            const __half* __restrict__ W0, const __half* __restrict__ W1,
            const __half* __restrict__ W2,
            const float* __restrict__ bi0, const float* __restrict__ bi1,
            const float* __restrict__ bi2,
            __half* __restrict__ C0, __half* __restrict__ C1,
            __half* __restrict__ C2,
            float* __restrict__ Cf)
{
    extern __shared__ __align__(16) __half dsm[];

    const int z = PROJ ? blockIdx.z : 0;
    const __half* Ag   = (z == 0) ? A0  : (z == 1) ? A1  : A2;
    const __half* W    = (z == 0) ? W0  : (z == 1) ? W1  : W2;
    const float*  bias = (z == 0) ? bi0 : (z == 1) ? bi1 : bi2;
    __half* Ch         = (z == 0) ? C0  : (z == 1) ? C1  : C2;

    const int tid  = threadIdx.x;
    const int lane = tid & 31;
    const int warp = tid >> 5;
    const int g    = lane >> 2;
    const int tig  = lane & 3;
    const int wm   = (warp >> 2) * 64;
    const int wn   = (warp & 3) * 32;
    const int bm   = blockIdx.y * 128;
    const int bn   = blockIdx.x * 128;
    const int lm_r = (lane & 7) + ((lane >> 3) & 1) * 8;
    const int lm_c = (lane >> 4) * 8;

    float acc[4][4][4];
    #pragma unroll
    for (int i = 0; i < 4; i++)
        #pragma unroll
        for (int j = 0; j < 4; j++)
            #pragma unroll
            for (int t = 0; t < 4; t++) acc[i][j][t] = 0.0f;

    auto load_tile = [&](int kt, int s) {
        __half* base = dsm + s * G_ST;
        const int k0 = kt * GBK;
        // A: 128 rows x 4 chunks = 512 chunks, 2/thread
        #pragma unroll
        for (int i = 0; i < 2; i++) {
            int p   = tid + i * 256;
            int row = p >> 2;
            int c   = (p & 3) * 8;
            cp_async16(smem_u32(base + row * ASTR + c),
                       Ag + (size_t)(bm + row) * D_MODEL + k0 + c);
        }
        // B: 32 rows x 16 chunks = 512 chunks, 2/thread
        #pragma unroll
        for (int i = 0; i < 2; i++) {
            int p   = tid + i * 256;
            int row = p >> 4;
            int c   = (p & 15) * 8;
            cp_async16(smem_u32(base + G_A + row * BSTR + c),
                       W + (size_t)(k0 + row) * D_MODEL + bn + c);
        }
    };

    load_tile(0, 0); cp_commit();
    load_tile(1, 1); cp_commit();

    for (int kt = 0; kt < G_NK; kt++) {
        const int s = kt & 1;
        if (kt == G_NK - 1) cp_wait<0>(); else cp_wait<1>();
        __syncthreads();
        __half* sA = dsm + s * G_ST;
        __half* sB = sA + G_A;

        #pragma unroll
        for (int ks = 0; ks < 2; ks++) {
            uint32_t ah[4][4], bh[4][2];
            #pragma unroll
            for (int i = 0; i < 4; i++) {
                uint32_t ad = smem_u32(sA + (wm + i * 16 + lm_r) * ASTR + ks * 16 + lm_c);
                ldsm_x4(ad, ah[i][0], ah[i][1], ah[i][2], ah[i][3]);
            }
            #pragma unroll
            for (int j2 = 0; j2 < 2; j2++) {
                uint32_t bd = smem_u32(sB + (ks * 16 + lm_r) * BSTR + wn + j2 * 16 + lm_c);
                ldsm_x4_t(bd, bh[2*j2][0], bh[2*j2][1], bh[2*j2+1][0], bh[2*j2+1][1]);
            }
            #pragma unroll
            for (int i = 0; i < 4; i++)
                #pragma unroll
                for (int j = 0; j < 4; j++) mma_h(acc[i][j], ah[i], bh[j]);
        }
        __syncthreads();
        if (kt + 2 < G_NK) load_tile(kt + 2, s);
        cp_commit();
    }

    #pragma unroll
    for (int i = 0; i < 4; i++) {
        int r0 = bm + wm + i * 16 + g;
        #pragma unroll
        for (int j = 0; j < 4; j++) {
            int c = bn + wn + j * 8 + tig * 2;
            float b0 = bias[c], b1 = bias[c + 1];
            float x0 = acc[i][j][0] + b0, y0 = acc[i][j][1] + b1;
            float x1 = acc[i][j][2] + b0, y1 = acc[i][j][3] + b1;
            size_t a0 = (size_t)r0 * D_MODEL + c;
            size_t a1 = (size_t)(r0 + 8) * D_MODEL + c;
            if (PROJ) {
                *(uint32_t*)&Ch[a0] = pack_h(x0, y0);
                *(uint32_t*)&Ch[a1] = pack_h(x1, y1);
            } else {
                *(float2*)&Cf[a0] = make_float2(x0, y0);
                *(float2*)&Cf[a1] = make_float2(x1, y1);
            }
        }
    }
}

// ---------------------------------------------------------------------------
// Flash attention, all fp16 operands. Single-pass QK^T and PV.
// FMA-fused exp2 softmax with conditional rescale. 2-stage cp.async K/V.
// ---------------------------------------------------------------------------
#define QBLK 128
#define KBLK 64
#define KSTR 72
#define KV_ARR (KBLK * KSTR)
#define KV_ST  (2 * KV_ARR)
#define A_SMEMB (2 * KV_ST * 2)
#define A_NK (SEQ / KBLK)

__global__ __launch_bounds__(256, 2)
void attn_h(const __half* __restrict__ Qhg,
            const __half* __restrict__ Khg, const __half* __restrict__ Vhg,
            __half* __restrict__ Ohg)
{
    extern __shared__ __align__(16) __half dsm[];

    const int tid  = threadIdx.x;
    const int lane = tid & 31;
    const int warp = tid >> 5;
    const int g    = lane >> 2;
    const int tig  = lane & 3;
    const int lm_r = (lane & 7) + ((lane >> 3) & 1) * 8;
    const int lm_c = (lane >> 4) * 8;
    const int kf_key = ((lane >> 4) & 1) * 8 + (lane & 7);
    const int kf_col = ((lane >> 3) & 1) * 8;

    const int b  = blockIdx.z;
    const int h  = blockIdx.y;
    const int q0 = blockIdx.x * QBLK;
    const size_t qbase = ((size_t)(b * SEQ + q0)) * D_MODEL + h * DHEAD;
    const float SC = 0.125f * 1.44269504088896f;   // 1/sqrt(64) * log2(e)

    // ---- Q staging (hi only) then register fragments ----
    #pragma unroll
    for (int i = 0; i < 4; i++) {
        int idx = tid + i * 256;              // 0..1023
        int row = idx >> 3;                   // 0..127
        int c   = (idx & 7) * 8;
        *(uint4*)&dsm[row * KSTR + c] =
            *(const uint4*)&Qhg[qbase + (size_t)row * D_MODEL + c];
    }
    __syncthreads();
    uint32_t qh[4][4];
    #pragma unroll
    for (int ks = 0; ks < 4; ks++) {
        uint32_t ad = smem_u32(&dsm[(warp * 16 + lm_r) * KSTR + ks * 16 + lm_c]);
        ldsm_x4(ad, qh[ks][0], qh[ks][1], qh[ks][2], qh[ks][3]);
    }
    __syncthreads();

    auto prefetch = [&](int kt, int s) {
        __half* base = dsm + s * KV_ST;
        const size_t gk = ((size_t)(b * SEQ + kt * KBLK)) * D_MODEL + h * DHEAD;
        #pragma unroll
        for (int i = 0; i < 4; i++) {
            int idx = tid + i * 256;
            int arr = idx >> 9;
            int rem = idx & 511;
            int row = rem >> 3;
            int c   = (rem & 7) * 8;
            const __half* src = arr ? Vhg : Khg;
            cp_async16(smem_u32(base + arr * KV_ARR + row * KSTR + c),
                       src + gk + (size_t)row * D_MODEL + c);
        }
    };

    float out[8][4];
    #pragma unroll
    for (int j = 0; j < 8; j++)
        #pragma unroll
        for (int t = 0; t < 4; t++) out[j][t] = 0.0f;
    float mrow[2] = {-INFINITY, -INFINITY};   // log2 units
    float lrow[2] = {0.0f, 0.0f};

    prefetch(0, 0); cp_commit();
    prefetch(1, 1); cp_commit();

    for (int kt = 0; kt < A_NK; kt++) {
        const int s = kt & 1;
        if (kt == A_NK - 1) cp_wait<0>(); else cp_wait<1>();
        __syncthreads();
        __half* sK = dsm + s * KV_ST;
        __half* sV = sK + KV_ARR;

        // ---- QK^T (single pass) ----
        float sc[8][4];
        #pragma unroll
        for (int j = 0; j < 8; j++)
            #pragma unroll
            for (int t = 0; t < 4; t++) sc[j][t] = 0.0f;

        #pragma unroll
        for (int ks = 0; ks < 4; ks++) {
            uint32_t bh[8][2];
            const int dd = ks * 16 + kf_col;
            #pragma unroll
            for (int jp = 0; jp < 4; jp++) {
                uint32_t ad = smem_u32(sK + (jp * 16 + kf_key) * KSTR + dd);
                ldsm_x4(ad, bh[2*jp][0], bh[2*jp][1], bh[2*jp+1][0], bh[2*jp+1][1]);
            }
            #pragma unroll
            for (int j = 0; j < 8; j++) mma_h(sc[j], qh[ks], bh[j]);
        }

        // ---- online softmax: max on raw scores, exp2(s*SC - m) via FMA ----
        #pragma unroll
        for (int r = 0; r < 2; r++) {
            float mx = -INFINITY;
            #pragma unroll
            for (int j = 0; j < 8; j++) {
                mx = fmaxf(mx, sc[j][2 * r]);
                mx = fmaxf(mx, sc[j][2 * r + 1]);
            }
            mx = fmaxf(mx, __shfl_xor_sync(0xFFFFFFFFu, mx, 1));
            mx = fmaxf(mx, __shfl_xor_sync(0xFFFFFFFFu, mx, 2));
            const float mx2 = mx * SC;
            float lsum = 0.0f;
            if (mx2 > mrow[r]) {
                const float corr = exp2f(mrow[r] - mx2);
                mrow[r] = mx2;
                #pragma unroll
                for (int j = 0; j < 8; j++) {
                    out[j][2 * r]     *= corr;
                    out[j][2 * r + 1] *= corr;
                }
                lrow[r] *= corr;
            }
            const float nm = mrow[r];
            #pragma unroll
            for (int j = 0; j < 8; j++) {
                float e0 = exp2f(fmaf(sc[j][2 * r],     SC, -nm));
                float e1 = exp2f(fmaf(sc[j][2 * r + 1], SC, -nm));
                sc[j][2 * r] = e0; sc[j][2 * r + 1] = e1;
                lsum += e0 + e1;
            }
            lrow[r] += lsum;
        }

        // ---- P @ V (single-pass fp16 P) ----
        #pragma unroll
        for (int ss = 0; ss < 4; ss++) {
            uint32_t ph[4];
            ph[0] = pack_h(sc[2 * ss][0],     sc[2 * ss][1]);
            ph[1] = pack_h(sc[2 * ss][2],     sc[2 * ss][3]);
            ph[2] = pack_h(sc[2 * ss + 1][0], sc[2 * ss + 1][1]);
            ph[3] = pack_h(sc[2 * ss + 1][2], sc[2 * ss + 1][3]);

            uint32_t vh[8][2];
            #pragma unroll
            for (int j2 = 0; j2 < 4; j2++) {
                uint32_t vd = smem_u32(sV + (ss * 16 + lm_r) * KSTR + j2 * 16 + lm_c);
                ldsm_x4_t(vd, vh[2*j2][0], vh[2*j2][1], vh[2*j2+1][0], vh[2*j2+1][1]);
            }
            #pragma unroll
            for (int j = 0; j < 8; j++) mma_h(out[j], ph, vh[j]);
        }
        __syncthreads();
        if (kt + 2 < A_NK) prefetch(kt + 2, s);
        cp_commit();
    }

    // ---- finalize ----
    #pragma unroll
    for (int r = 0; r < 2; r++) {
        lrow[r] += __shfl_xor_sync(0xFFFFFFFFu, lrow[r], 1);
        lrow[r] += __shfl_xor_sync(0xFFFFFFFFu, lrow[r], 2);
    }
    const float inv0 = 1.0f / lrow[0];
    const float inv1 = 1.0f / lrow[1];
    const int row0 = q0 + warp * 16 + g;
    #pragma unroll
    for (int j = 0; j < 8; j++) {
        int d = j * 8 + tig * 2;
        size_t addr = ((size_t)(b * SEQ + row0)) * D_MODEL + h * DHEAD + d;
        *(uint32_t*)&Ohg[addr]               = pack_h(out[j][0] * inv0, out[j][1] * inv0);
        *(uint32_t*)&Ohg[addr + 8 * D_MODEL] = pack_h(out[j][2] * inv1, out[j][3] * inv1);
    }
}

// ---------------------------------------------------------------------------
// Launch
// ---------------------------------------------------------------------------
extern "C" void kernel_launch(void* const* d_in, const int* in_sizes, int n_in,
                              void* d_out, int out_size)
{
    const float* queries = (const float*)d_in[0];
    const float* keys    = (const float*)d_in[1];
    const float* values  = (const float*)d_in[2];
    const float* Wq      = (const float*)d_in[3];
    const float* bq      = (const float*)d_in[4];
    const float* Wk      = (const float*)d_in[5];
    const float* bk      = (const float*)d_in[6];
    const float* Wv      = (const float*)d_in[7];
    const float* bv      = (const float*)d_in[8];
    const float* Wo      = (const float*)d_in[9];
    const float* bo      = (const float*)d_in[10];
    float* out = (float*)d_out;

    __half *wq, *wk, *wv, *wo, *qh, *kh, *vh, *oh;
    __half *x0, *x1, *x2;
    cudaGetSymbolAddress((void**)&wq, g_wq);
    cudaGetSymbolAddress((void**)&wk, g_wk);
    cudaGetSymbolAddress((void**)&wv, g_wv);
    cudaGetSymbolAddress((void**)&wo, g_wo);
    cudaGetSymbolAddress((void**)&qh, g_qh);
    cudaGetSymbolAddress((void**)&kh, g_kh);
    cudaGetSymbolAddress((void**)&vh, g_vh);
    cudaGetSymbolAddress((void**)&oh, g_oh);
    {
        __half* base;
        cudaGetSymbolAddress((void**)&base, g_x);
        x0 = base; x1 = base + NACT; x2 = base + 2 * NACT;
    }

    cudaFuncSetAttribute((const void*)gemm_u<true>,
                         cudaFuncAttributeMaxDynamicSharedMemorySize, G_SMEMB);
    cudaFuncSetAttribute((const void*)gemm_u<false>,
                         cudaFuncAttributeMaxDynamicSharedMemorySize, G_SMEMB);
    cudaFuncSetAttribute((const void*)attn_h,
                         cudaFuncAttributeMaxDynamicSharedMemorySize, A_SMEMB);

    // 1) round everything to fp16: grid.x sized for NACT (largest); NW blocks
    //    exit early via bounds check.
    round7<<<dim3((unsigned)(NACT / (256 * 8)), 7), 256>>>(
        Wq, Wk, Wv, Wo, queries, keys, values,
        wq, wk, wv, wo, x0, x1, x2);

    // 2) fused Q/K/V projections (single-pass fp16)
    gemm_u<true><<<dim3(D_MODEL / 128, MROWS / 128, 3), 256, G_SMEMB>>>(
        x0, x1, x2, wq, wk, wv, bq, bk, bv, qh, kh, vh, nullptr);

    // 3) attention
    attn_h<<<dim3(SEQ / QBLK, NH, BATCH), 256, A_SMEMB>>>(qh, kh, vh, oh);

    // 4) output projection (fp32 out)
    gemm_u<false><<<dim3(D_MODEL / 128, MROWS / 128, 1), 256, G_SMEMB>>>(
        oh, nullptr, nullptr, wo, nullptr, nullptr,
        bo, nullptr, nullptr, nullptr, nullptr, nullptr, out);
}

// round 11
// speedup vs baseline: 2.6387x; 1.0395x over previous
#include <cuda_runtime.h>
#include <cuda_fp16.h>
#include <math.h>
#include <stdint.h>

#define D_MODEL 1024
#define NH      16
#define DHEAD   64
#define BATCH   4
#define SEQ     1024
#define MROWS   (BATCH * SEQ)   // 4096

// ---------------------------------------------------------------------------
// Scratch (static device globals). fp16.
// ---------------------------------------------------------------------------
#define NACT ((size_t)MROWS * D_MODEL)   // 4M
#define NW   ((size_t)D_MODEL * D_MODEL) // 1M
__device__ __half g_wq[NW], g_wk[NW], g_wv[NW], g_wo[NW];   // [K,N] fp16
__device__ __half g_x[3][NACT];                             // rounded activations
__device__ __half g_qh[NACT];                               // Q fp16
__device__ __half g_kh[NACT];                               // K fp16
__device__ __half g_vh[NACT];                               // V fp16
__device__ __half g_oh[NACT];                               // attn out fp16

// ---------------------------------------------------------------------------
// Helpers
// ---------------------------------------------------------------------------
__device__ __forceinline__ uint32_t smem_u32(const void* p) {
    return (uint32_t)__cvta_generic_to_shared(p);
}
__device__ __forceinline__ void cp_async16(uint32_t dst, const void* src) {
    asm volatile("cp.async.cg.shared.global [%0], [%1], 16;" :: "r"(dst), "l"(src));
}
__device__ __forceinline__ void cp_commit() {
    asm volatile("cp.async.commit_group;");
}
template <int N>
__device__ __forceinline__ void cp_wait() {
    asm volatile("cp.async.wait_group %0;" :: "n"(N));
}
__device__ __forceinline__ void ldsm_x4(uint32_t addr, uint32_t& r0, uint32_t& r1,
                                        uint32_t& r2, uint32_t& r3) {
    asm volatile("ldmatrix.sync.aligned.m8n8.x4.shared.b16 {%0,%1,%2,%3}, [%4];"
                 : "=r"(r0), "=r"(r1), "=r"(r2), "=r"(r3) : "r"(addr));
}
__device__ __forceinline__ void ldsm_x4_t(uint32_t addr, uint32_t& r0, uint32_t& r1,
                                          uint32_t& r2, uint32_t& r3) {
    asm volatile("ldmatrix.sync.aligned.m8n8.x4.trans.shared.b16 {%0,%1,%2,%3}, [%4];"
                 : "=r"(r0), "=r"(r1), "=r"(r2), "=r"(r3) : "r"(addr));
}
__device__ __forceinline__ void mma_h(float c[4], const uint32_t a[4], const uint32_t b[2]) {
    asm volatile(
        "mma.sync.aligned.m16n8k16.row.col.f32.f16.f16.f32 "
        "{%0,%1,%2,%3}, {%4,%5,%6,%7}, {%8,%9}, {%0,%1,%2,%3};"
        : "+f"(c[0]), "+f"(c[1]), "+f"(c[2]), "+f"(c[3])
        : "r"(a[0]), "r"(a[1]), "r"(a[2]), "r"(a[3]), "r"(b[0]), "r"(b[1]));
}
__device__ __forceinline__ uint32_t pack_h(float x, float y) {
    __half2 h2; h2.x = __float2half_rn(x); h2.y = __float2half_rn(y);
    return *reinterpret_cast<uint32_t*>(&h2);
}

// ---------------------------------------------------------------------------
// Preprocessing: round 4 weights + 3 activations to fp16 (blockIdx.y selects).
// ---------------------------------------------------------------------------
__global__ __launch_bounds__(256)
void round7(const float* __restrict__ w0, const float* __restrict__ w1,
            const float* __restrict__ w2, const float* __restrict__ w3,
            const float* __restrict__ a0, const float* __restrict__ a1,
            const float* __restrict__ a2,
            __half* __restrict__ ow0, __half* __restrict__ ow1,
            __half* __restrict__ ow2, __half* __restrict__ ow3,
            __half* __restrict__ oa0, __half* __restrict__ oa1,
            __half* __restrict__ oa2)
{
    const int y = blockIdx.y;
    const float* src;
    __half* dst;
    size_t n;
    switch (y) {
        case 0: src = w0; dst = ow0; n = NW;   break;
        case 1: src = w1; dst = ow1; n = NW;   break;
        case 2: src = w2; dst = ow2; n = NW;   break;
        case 3: src = w3; dst = ow3; n = NW;   break;
        case 4: src = a0; dst = oa0; n = NACT; break;
        case 5: src = a1; dst = oa1; n = NACT; break;
        default: src = a2; dst = oa2; n = NACT; break;
    }
    size_t i = ((size_t)blockIdx.x * 256 + threadIdx.x) * 8;
    if (i >= n) return;
    float4 a = *(const float4*)&src[i];
    float4 b = *(const float4*)&src[i + 4];
    uint4 o;
    o.x = pack_h(a.x, a.y); o.y = pack_h(a.z, a.w);
    o.z = pack_h(b.x, b.y); o.w = pack_h(b.z, b.w);
    *(uint4*)&dst[i] = o;
}

// ---------------------------------------------------------------------------
// Unified single-pass fp16 GEMM: C = A @ W + bias. 128x128x64 tiles,
// 2-stage cp.async (16 barriers total). PROJ: fused QKV. !PROJ: fp32 out.
// ---------------------------------------------------------------------------
#define GBK  64
#define ASTR 72     // 64 halfs + pad
#define BSTR 136    // 128 halfs + pad
#define G_A  (128 * ASTR)            // 9216 halfs
#define G_B  (GBK * BSTR)            // 8704 halfs
#define G_ST (G_A + G_B)             // 17920 halfs per stage
#define G_SMEMB (2 * G_ST * 2)       // 71680 B
#define G_NK (D_MODEL / GBK)         // 16

template <bool PROJ>
__global__ __launch_bounds__(256, 2)
void gemm_u(const __half* __restrict__ A0, const __half* __restrict__ A1,
            const __half* __restrict__ A2,
            const __half* __restrict__ W0, const __half* __restrict__ W1,
            const __half* __restrict__ W2,
            const float* __restrict__ bi0, const float* __restrict__ bi1,
            const float* __restrict__ bi2,
            __half* __restrict__ C0, __half* __restrict__ C1,
            __half* __restrict__ C2,
            float* __restrict__ Cf)
{
    extern __shared__ __align__(16) __half dsm[];

    const int z = PROJ ? blockIdx.z : 0;
    const __half* Ag   = (z == 0) ? A0  : (z == 1) ? A1  : A2;
    const __half* W    = (z == 0) ? W0  : (z == 1) ? W1  : W2;
    const float*  bias = (z == 0) ? bi0 : (z == 1) ? bi1 : bi2;
    __half* Ch         = (z == 0) ? C0  : (z == 1) ? C1  : C2;

    const int tid  = threadIdx.x;
    const int lane = tid & 31;
    const int warp = tid >> 5;
    const int g    = lane >> 2;
    const int tig  = lane & 3;
    const int wm   = (warp >> 2) * 64;
    const int wn   = (warp & 3) * 32;
    const int bm   = blockIdx.y * 128;
    const int bn   = blockIdx.x * 128;
    const int lm_r = (lane & 7) + ((lane >> 3) & 1) * 8;
    const int lm_c = (lane >> 4) * 8;

    float acc[4][4][4];
    #pragma unroll
    for (int i = 0; i < 4; i++)
        #pragma unroll
        for (int j = 0; j < 4; j++)
            #pragma unroll
            for (int t = 0; t < 4; t++) acc[i][j][t] = 0.0f;

    auto load_tile = [&](int kt, int s) {
        __half* base = dsm + s * G_ST;
        const int k0 = kt * GBK;
        // A: 128 rows x 8 chunks = 1024 chunks, 4/thread
        #pragma unroll
        for (int i = 0; i < 4; i++) {
            int p   = tid + i * 256;
            int row = p >> 3;
            int c   = (p & 7) * 8;
            cp_async16(smem_u32(base + row * ASTR + c),
                       Ag + (size_t)(bm + row) * D_MODEL + k0 + c);
        }
        // B: 64 rows x 16 chunks = 1024 chunks, 4/thread
        #pragma unroll
        for (int i = 0; i < 4; i++) {
            int p   = tid + i * 256;
            int row = p >> 4;
            int c   = (p & 15) * 8;
            cp_async16(smem_u32(base + G_A + row * BSTR + c),
                       W + (size_t)(k0 + row) * D_MODEL + bn + c);
        }
    };

    load_tile(0, 0); cp_commit();
    load_tile(1, 1); cp_commit();

    for (int kt = 0; kt < G_NK; kt++) {
        const int s = kt & 1;
        if (kt == G_NK - 1) cp_wait<0>(); else cp_wait<1>();
        __syncthreads();
        __half* sA = dsm + s * G_ST;
        __half* sB = sA + G_A;

        #pragma unroll
        for (int ks = 0; ks < 4; ks++) {
            uint32_t ah[4][4], bh[4][2];
            #pragma unroll
            for (int i = 0; i < 4; i++) {
                uint32_t ad = smem_u32(sA + (wm + i * 16 + lm_r) * ASTR + ks * 16 + lm_c);
                ldsm_x4(ad, ah[i][0], ah[i][1], ah[i][2], ah[i][3]);
            }
            #pragma unroll
            for (int j2 = 0; j2 < 2; j2++) {
                uint32_t bd = smem_u32(sB + (ks * 16 + lm_r) * BSTR + wn + j2 * 16 + lm_c);
                ldsm_x4_t(bd, bh[2*j2][0], bh[2*j2][1], bh[2*j2+1][0], bh[2*j2+1][1]);
            }
            #pragma unroll
            for (int i = 0; i < 4; i++)
                #pragma unroll
                for (int j = 0; j < 4; j++) mma_h(acc[i][j], ah[i], bh[j]);
        }
        __syncthreads();
        if (kt + 2 < G_NK) load_tile(kt + 2, s);
        cp_commit();
    }

    #pragma unroll
    for (int i = 0; i < 4; i++) {
        int r0 = bm + wm + i * 16 + g;
        #pragma unroll
        for (int j = 0; j < 4; j++) {
            int c = bn + wn + j * 8 + tig * 2;
            float b0 = bias[c], b1 = bias[c + 1];
            float x0 = acc[i][j][0] + b0, y0 = acc[i][j][1] + b1;
            float x1 = acc[i][j][2] + b0, y1 = acc[i][j][3] + b1;
            size_t a0 = (size_t)r0 * D_MODEL + c;
            size_t a1 = (size_t)(r0 + 8) * D_MODEL + c;
            if (PROJ) {
                *(uint32_t*)&Ch[a0] = pack_h(x0, y0);
                *(uint32_t*)&Ch[a1] = pack_h(x1, y1);
            } else {
                *(float2*)&Cf[a0] = make_float2(x0, y0);
                *(float2*)&Cf[a1] = make_float2(x1, y1);
            }
        }
    }
}

// ---------------------------------------------------------------------------
// Flash attention, all fp16 operands. Single-pass QK^T and PV.
// FMA-fused exp2 softmax, conditional rescale. 3-stage cp.async K/V pipeline.
// ---------------------------------------------------------------------------
#define QBLK 128
#define KBLK 64
#define KSTR 72
#define KV_ARR (KBLK * KSTR)          // 4608 halfs
#define KV_ST  (2 * KV_ARR)           // 9216 halfs per stage
#define A_NSTG 3
#define A_SMEMB (A_NSTG * KV_ST * 2)  // 55296 B
#define A_NK (SEQ / KBLK)             // 16

__global__ __launch_bounds__(256, 2)
void attn_h(const __half* __restrict__ Qhg,
            const __half* __restrict__ Khg, const __half* __restrict__ Vhg,
            __half* __restrict__ Ohg)
{
    extern __shared__ __align__(16) __half dsm[];

    const int tid  = threadIdx.x;
    const int lane = tid & 31;
    const int warp = tid >> 5;
    const int g    = lane >> 2;
    const int tig  = lane & 3;
    const int lm_r = (lane & 7) + ((lane >> 3) & 1) * 8;
    const int lm_c = (lane >> 4) * 8;
    const int kf_key = ((lane >> 4) & 1) * 8 + (lane & 7);
    const int kf_col = ((lane >> 3) & 1) * 8;

    const int b  = blockIdx.z;
    const int h  = blockIdx.y;
    const int q0 = blockIdx.x * QBLK;
    const size_t qbase = ((size_t)(b * SEQ + q0)) * D_MODEL + h * DHEAD;
    const float SC = 0.125f * 1.44269504088896f;   // 1/sqrt(64) * log2(e)

    // ---- Q staging (fits in stage 0) then register fragments ----
    #pragma unroll
    for (int i = 0; i < 4; i++) {
        int idx = tid + i * 256;
        int row = idx >> 3;
        int c   = (idx & 7) * 8;
        *(uint4*)&dsm[row * KSTR + c] =
            *(const uint4*)&Qhg[qbase + (size_t)row * D_MODEL + c];
    }
    __syncthreads();
    uint32_t qh[4][4];
    #pragma unroll
    for (int ks = 0; ks < 4; ks++) {
        uint32_t ad = smem_u32(&dsm[(warp * 16 + lm_r) * KSTR + ks * 16 + lm_c]);
        ldsm_x4(ad, qh[ks][0], qh[ks][1], qh[ks][2], qh[ks][3]);
    }
    __syncthreads();

    auto prefetch = [&](int kt, int s) {
        __half* base = dsm + s * KV_ST;
        const size_t gk = ((size_t)(b * SEQ + kt * KBLK)) * D_MODEL + h * DHEAD;
        #pragma unroll
        for (int i = 0; i < 4; i++) {
            int idx = tid + i * 256;
            int arr = idx >> 9;
            int rem = idx & 511;
            int row = rem >> 3;
            int c   = (rem & 7) * 8;
            const __half* src = arr ? Vhg : Khg;
            cp_async16(smem_u32(base + arr * KV_ARR + row * KSTR + c),
                       src + gk + (size_t)row * D_MODEL + c);
        }
    };

    float out[8][4];
    #pragma unroll
    for (int j = 0; j < 8; j++)
        #pragma unroll
        for (int t = 0; t < 4; t++) out[j][t] = 0.0f;
    float mrow[2] = {-INFINITY, -INFINITY};
    float lrow[2] = {0.0f, 0.0f};

    prefetch(0, 0); cp_commit();
    prefetch(1, 1); cp_commit();
    prefetch(2, 2); cp_commit();

    int s = 0;
    for (int kt = 0; kt < A_NK; kt++) {
        cp_wait<2>();
        __syncthreads();
        __half* sK = dsm + s * KV_ST;
        __half* sV = sK + KV_ARR;

        // ---- QK^T ----
        float sc[8][4];
        #pragma unroll
        for (int j = 0; j < 8; j++)
            #pragma unroll
            for (int t = 0; t < 4; t++) sc[j][t] = 0.0f;

        #pragma unroll
        for (int ks = 0; ks < 4; ks++) {
            uint32_t bh[8][2];
            const int dd = ks * 16 + kf_col;
            #pragma unroll
            for (int jp = 0; jp < 4; jp++) {
                uint32_t ad = smem_u32(sK + (jp * 16 + kf_key) * KSTR + dd);
                ldsm_x4(ad, bh[2*jp][0], bh[2*jp][1], bh[2*jp+1][0], bh[2*jp+1][1]);
            }
            #pragma unroll
            for (int j = 0; j < 8; j++) mma_h(sc[j], qh[ks], bh[j]);
        }

        // ---- online softmax ----
        #pragma unroll
        for (int r = 0; r < 2; r++) {
            float mx = -INFINITY;
            #pragma unroll
            for (int j = 0; j < 8; j++) {
                mx = fmaxf(mx, sc[j][2 * r]);
                mx = fmaxf(mx, sc[j][2 * r + 1]);
            }
            mx = fmaxf(mx, __shfl_xor_sync(0xFFFFFFFFu, mx, 1));
            mx = fmaxf(mx, __shfl_xor_sync(0xFFFFFFFFu, mx, 2));
            const float mx2 = mx * SC;
            float lsum = 0.0f;
            if (mx2 > mrow[r]) {
                const float corr = exp2f(mrow[r] - mx2);
                mrow[r] = mx2;
                #pragma unroll
                for (int j = 0; j < 8; j++) {
                    out[j][2 * r]     *= corr;
                    out[j][2 * r + 1] *= corr;
                }
                lrow[r] *= corr;
            }
            const float nm = mrow[r];
            #pragma unroll
            for (int j = 0; j < 8; j++) {
                float e0 = exp2f(fmaf(sc[j][2 * r],     SC, -nm));
                float e1 = exp2f(fmaf(sc[j][2 * r + 1], SC, -nm));
                sc[j][2 * r] = e0; sc[j][2 * r + 1] = e1;
                lsum += e0 + e1;
            }
            lrow[r] += lsum;
        }

        // ---- P @ V ----
        #pragma unroll
        for (int ss = 0; ss < 4; ss++) {
            uint32_t ph[4];
            ph[0] = pack_h(sc[2 * ss][0],     sc[2 * ss][1]);
            ph[1] = pack_h(sc[2 * ss][2],     sc[2 * ss][3]);
            ph[2] = pack_h(sc[2 * ss + 1][0], sc[2 * ss + 1][1]);
            ph[3] = pack_h(sc[2 * ss + 1][2], sc[2 * ss + 1][3]);

            uint32_t vh[8][2];
            #pragma unroll
            for (int j2 = 0; j2 < 4; j2++) {
                uint32_t vd = smem_u32(sV + (ss * 16 + lm_r) * KSTR + j2 * 16 + lm_c);
                ldsm_x4_t(vd, vh[2*j2][0], vh[2*j2][1], vh[2*j2+1][0], vh[2*j2+1][1]);
            }
            #pragma unroll
            for (int j = 0; j < 8; j++) mma_h(out[j], ph, vh[j]);
        }
        __syncthreads();
        if (kt + A_NSTG < A_NK) prefetch(kt + A_NSTG, s);
        cp_commit();
        s = (s == A_NSTG - 1) ? 0 : s + 1;
    }

    // ---- finalize ----
    #pragma unroll
    for (int r = 0; r < 2; r++) {
        lrow[r] += __shfl_xor_sync(0xFFFFFFFFu, lrow[r], 1);
        lrow[r] += __shfl_xor_sync(0xFFFFFFFFu, lrow[r], 2);
    }
    const float inv0 = 1.0f / lrow[0];
    const float inv1 = 1.0f / lrow[1];
    const int row0 = q0 + warp * 16 + g;
    #pragma unroll
    for (int j = 0; j < 8; j++) {
        int d = j * 8 + tig * 2;
        size_t addr = ((size_t)(b * SEQ + row0)) * D_MODEL + h * DHEAD + d;
        *(uint32_t*)&Ohg[addr]               = pack_h(out[j][0] * inv0, out[j][1] * inv0);
        *(uint32_t*)&Ohg[addr + 8 * D_MODEL] = pack_h(out[j][2] * inv1, out[j][3] * inv1);
    }
}

// ---------------------------------------------------------------------------
// Launch
// ---------------------------------------------------------------------------
extern "C" void kernel_launch(void* const* d_in, const int* in_sizes, int n_in,
                              void* d_out, int out_size)
{
    const float* queries = (const float*)d_in[0];
    const float* keys    = (const float*)d_in[1];
    const float* values  = (const float*)d_in[2];
    const float* Wq      = (const float*)d_in[3];
    const float* bq      = (const float*)d_in[4];
    const float* Wk      = (const float*)d_in[5];
    const float* bk      = (const float*)d_in[6];
    const float* Wv      = (const float*)d_in[7];
    const float* bv      = (const float*)d_in[8];
    const float* Wo      = (const float*)d_in[9];
    const float* bo      = (const float*)d_in[10];
    float* out = (float*)d_out;

    __half *wq, *wk, *wv, *wo, *qh, *kh, *vh, *oh;
    __half *x0, *x1, *x2;
    cudaGetSymbolAddress((void**)&wq, g_wq);
    cudaGetSymbolAddress((void**)&wk, g_wk);
    cudaGetSymbolAddress((void**)&wv, g_wv);
    cudaGetSymbolAddress((void**)&wo, g_wo);
    cudaGetSymbolAddress((void**)&qh, g_qh);
    cudaGetSymbolAddress((void**)&kh, g_kh);
    cudaGetSymbolAddress((void**)&vh, g_vh);
    cudaGetSymbolAddress((void**)&oh, g_oh);
    {
        __half* base;
        cudaGetSymbolAddress((void**)&base, g_x);
        x0 = base; x1 = base + NACT; x2 = base + 2 * NACT;
    }

    cudaFuncSetAttribute((const void*)gemm_u<true>,
                         cudaFuncAttributeMaxDynamicSharedMemorySize, G_SMEMB);
    cudaFuncSetAttribute((const void*)gemm_u<false>,
                         cudaFuncAttributeMaxDynamicSharedMemorySize, G_SMEMB);
    cudaFuncSetAttribute((const void*)attn_h,
                         cudaFuncAttributeMaxDynamicSharedMemorySize, A_SMEMB);

    round7<<<dim3((unsigned)(NACT / (256 * 8)), 7), 256>>>(
        Wq, Wk, Wv, Wo, queries, keys, values,
        wq, wk, wv, wo, x0, x1, x2);

    gemm_u<true><<<dim3(D_MODEL / 128, MROWS / 128, 3), 256, G_SMEMB>>>(
        x0, x1, x2, wq, wk, wv, bq, bk, bv, qh, kh, vh, nullptr);

    attn_h<<<dim3(SEQ / QBLK, NH, BATCH), 256, A_SMEMB>>>(qh, kh, vh, oh);

    gemm_u<false><<<dim3(D_MODEL / 128, MROWS / 128, 1), 256, G_SMEMB>>>(
        oh, nullptr, nullptr, wo, nullptr, nullptr,
        bo, nullptr, nullptr, nullptr, nullptr, nullptr, out);
}